// round 9
// baseline (speedup 1.0000x reference)
#include <cuda_runtime.h>
#include <cstdint>

// Problem constants
#define N_ATOMS 20000
#define N_EDGES 640000
#define NB      128
#define N_RBF   20

// -------- device scratch --------
__device__ float g_h[N_ATOMS * NB];
__device__ float g_agg[N_ATOMS * NB];

__device__ __forceinline__ uint32_t to_tf32_bits(float x) {
    uint32_t r; asm("cvt.rna.tf32.f32 %0, %1;" : "=r"(r) : "f"(x)); return r;
}
__device__ __forceinline__ float to_tf32(float x) {
    return __uint_as_float(to_tf32_bits(x));
}
#define LN2F     0.69314718055994531f
#define LOG2EF   1.4426950408889634f
// softplus(x) - ln2 = max(x,0) + ln2*(lg2(1 + 2^(-|x|*log2e)) - 1)
__device__ __forceinline__ float ssp_fast(float x) {
    float u = fabsf(x) * -LOG2EF;
    float e; asm("ex2.approx.f32 %0, %1;" : "=f"(e) : "f"(u));
    float l; asm("lg2.approx.f32 %0, %1;" : "=f"(l) : "f"(1.0f + e));
    return fmaf(LN2F, l - 1.0f, fmaxf(x, 0.0f));
}

// m16n8k8 tf32 mma
__device__ __forceinline__ void mma16n8k8(float4& c,
                                          float a0, float a1, float a2, float a3,
                                          float b0, float b1) {
    asm volatile(
        "mma.sync.aligned.m16n8k8.row.col.f32.tf32.tf32.f32 "
        "{%0,%1,%2,%3}, {%4,%5,%6,%7}, {%8,%9}, {%0,%1,%2,%3};"
        : "+f"(c.x), "+f"(c.y), "+f"(c.z), "+f"(c.w)
        : "r"(__float_as_uint(a0)), "r"(__float_as_uint(a1)),
          "r"(__float_as_uint(a2)), "r"(__float_as_uint(a3)),
          "r"(__float_as_uint(b0)), "r"(__float_as_uint(b1)));
}

__device__ __forceinline__ void red_v4(float* p, float a, float b, float c, float d) {
    asm volatile("red.global.add.v4.f32 [%0], {%1, %2, %3, %4};"
                 :: "l"(p), "f"(a), "f"(b), "f"(c), "f"(d) : "memory");
}

// -------- zero kernel --------
__global__ void zero_kernel(float4* __restrict__ p, int n4) {
    int i = blockIdx.x * blockDim.x + threadIdx.x;
    if (i < n4) p[i] = make_float4(0.f, 0.f, 0.f, 0.f);
}

// -------- exact FFMA [rows,128]@[128,128] (h path), 8 rows/block --------
__global__ __launch_bounds__(128) void gemm128_kernel(
    const float* __restrict__ A, const float* __restrict__ W,
    float* __restrict__ C, int nrows)
{
    __shared__ float xs[8 * NB];
    const int row0 = blockIdx.x * 8;
    const int tid  = threadIdx.x;

    for (int i = tid; i < 8 * NB; i += 128) {
        int r = row0 + (i >> 7);
        xs[i] = (r < nrows) ? A[row0 * NB + i] : 0.0f;
    }
    __syncthreads();

    const int c = tid;
    float acc[8];
#pragma unroll
    for (int r = 0; r < 8; r++) acc[r] = 0.0f;

#pragma unroll 4
    for (int k = 0; k < NB; k++) {
        float w = W[k * NB + c];
#pragma unroll
        for (int r = 0; r < 8; r++) acc[r] += xs[r * NB + k] * w;
    }
#pragma unroll
    for (int r = 0; r < 8; r++) {
        int row = row0 + r;
        if (row < nrows) C[row * NB + c] = acc[r];
    }
}

// ======================= fused edge kernel (warp-decoupled) =======================
// 12 warps/CTA (384 threads — proven launch shape), each warp independently
// processes 16-edge groups.
//   layer1: c1(init=b1) += f@W1 (A direct from global, tf32 mma, K pad 20->24)
//           phi = tf32(ssp(c1)) -> warp-private smem
//   layer2: c2(init=b2) += phi@W2 (k-paired LDS.128 B fragments)
//   pair-swap into phi rows, then row-wise epilogue:
//   per edge: full h[idx_j] row load, red.v4 full row into agg[idx_i].
#define EW 12
#define ET (EW * 32)
// smem float offsets
#define E_W1Q 0           // 16*32*4  = 2048   (kt0+kt1 paired)
#define E_W1R 2048        // 16*32*2  = 1024   (kt2)
#define E_W2Q 3072        // 8*16*32*4 = 16384 (k-paired)
#define E_B1  19456       // 128
#define E_B2  19584       // 128
#define E_PHI 19712       // EW * 16*132 = 25344
#define E_SMEMF 45056
#define E_SMEMB (E_SMEMF * 4)

__global__ __launch_bounds__(ET, 1) void edge_kernel(
    const float* __restrict__ f_ij, const float* __restrict__ rcut,
    const int* __restrict__ idx_i, const int* __restrict__ idx_j,
    const float* __restrict__ W1, const float* __restrict__ b1,
    const float* __restrict__ W2, const float* __restrict__ b2)
{
    extern __shared__ float sm[];
    const int tid  = threadIdx.x;
    const int warp = tid >> 5;
    const int lane = tid & 31;
    const int g    = lane >> 2;
    const int t    = lane & 3;

    // ---- stage W1 paired fragments ----
    for (int i = tid; i < 16 * 32; i += ET) {
        int nt = i >> 5, l = i & 31;
        int gg = l >> 2, tt = l & 3;
        int n = nt * 8 + gg;
        // kt0 (k = tt, tt+4) and kt1 (k = 8+tt, 12+tt): all < 20
        sm[E_W1Q + i * 4 + 0] = to_tf32(W1[tt * NB + n]);
        sm[E_W1Q + i * 4 + 1] = to_tf32(W1[(tt + 4) * NB + n]);
        sm[E_W1Q + i * 4 + 2] = to_tf32(W1[(tt + 8) * NB + n]);
        sm[E_W1Q + i * 4 + 3] = to_tf32(W1[(tt + 12) * NB + n]);
        // kt2: k = 16+tt real, 20+tt padding (A side is zero there)
        sm[E_W1R + i * 2 + 0] = to_tf32(W1[(tt + 16) * NB + n]);
        sm[E_W1R + i * 2 + 1] = 0.0f;
    }
    // ---- stage W2 k-paired fragments (8 pairs x 16 nt) ----
    for (int i = tid; i < 8 * 16 * 32; i += ET) {
        int p = i >> 9, rem = i & 511, nt = rem >> 5, l = rem & 31;
        int gg = l >> 2, tt = l & 3;
        int n = nt * 8 + gg;
        int k0 = p * 16 + tt;
        sm[E_W2Q + i * 4 + 0] = to_tf32(W2[k0 * NB + n]);
        sm[E_W2Q + i * 4 + 1] = to_tf32(W2[(k0 + 4) * NB + n]);
        sm[E_W2Q + i * 4 + 2] = to_tf32(W2[(k0 + 8) * NB + n]);
        sm[E_W2Q + i * 4 + 3] = to_tf32(W2[(k0 + 12) * NB + n]);
    }
    for (int i = tid; i < NB; i += ET) {
        sm[E_B1 + i] = b1[i];
        sm[E_B2 + i] = b2[i];
    }
    __syncthreads();

    float* phw = sm + E_PHI + warp * (16 * 132);
    const int ngroups = N_EDGES / 16;  // 40000

    for (int grp = blockIdx.x * EW + warp; grp < ngroups; grp += gridDim.x * EW) {
        const int e0 = grp * 16;

        // edge metadata: lanes 0..15 hold one edge each
        float rc_l = 0.0f; int ji_l = 0, ii_l = 0;
        if (lane < 16) {
            rc_l = __ldg(rcut + e0 + lane);
            ji_l = __ldg(idx_j + e0 + lane);
            ii_l = __ldg(idx_i + e0 + lane);
        }

        // ---- layer 1: c1 = b1 + f @ W1 (A direct from global) ----
        {
            float4 c1[16];
#pragma unroll
            for (int nt = 0; nt < 16; nt++) {
                float2 bb = *(const float2*)(sm + E_B1 + nt * 8 + 2 * t);
                c1[nt].x = bb.x; c1[nt].y = bb.y;
                c1[nt].z = bb.x; c1[nt].w = bb.y;
            }
            const float* fr0 = f_ij + (size_t)(e0 + g) * N_RBF;
            const float* fr1 = fr0 + 8 * N_RBF;
            // kt0 + kt1 (paired B)
            float a00 = to_tf32(__ldg(fr0 + t));
            float a01 = to_tf32(__ldg(fr1 + t));
            float a02 = to_tf32(__ldg(fr0 + t + 4));
            float a03 = to_tf32(__ldg(fr1 + t + 4));
            float a10 = to_tf32(__ldg(fr0 + t + 8));
            float a11 = to_tf32(__ldg(fr1 + t + 8));
            float a12 = to_tf32(__ldg(fr0 + t + 12));
            float a13 = to_tf32(__ldg(fr1 + t + 12));
            // kt2 (cols 16..19 real, 20..23 zero)
            float a20 = to_tf32(__ldg(fr0 + t + 16));
            float a21 = to_tf32(__ldg(fr1 + t + 16));
            const float* bq = sm + E_W1Q + lane * 4;
            const float* br = sm + E_W1R + lane * 2;
#pragma unroll
            for (int nt = 0; nt < 16; nt++) {
                float4 b4 = *(const float4*)(bq + nt * 128);
                mma16n8k8(c1[nt], a00, a01, a02, a03, b4.x, b4.y);
                mma16n8k8(c1[nt], a10, a11, a12, a13, b4.z, b4.w);
                float2 b2f = *(const float2*)(br + nt * 64);
                mma16n8k8(c1[nt], a20, a21, 0.0f, 0.0f, b2f.x, b2f.y);
            }
            // ssp -> phi
#pragma unroll
            for (int nt = 0; nt < 16; nt++) {
                const int n0 = nt * 8 + 2 * t;
                float2 lo, hi;
                lo.x = to_tf32(ssp_fast(c1[nt].x));
                lo.y = to_tf32(ssp_fast(c1[nt].y));
                hi.x = to_tf32(ssp_fast(c1[nt].z));
                hi.y = to_tf32(ssp_fast(c1[nt].w));
                *(float2*)(phw + g * 132 + n0) = lo;
                *(float2*)(phw + (g + 8) * 132 + n0) = hi;
            }
        }
        __syncwarp();

        // ---- layer 2: c2 = b2 + phi @ W2 (k-paired) ----
        float4 c2[16];
#pragma unroll
        for (int nt = 0; nt < 16; nt++) {
            float2 bb = *(const float2*)(sm + E_B2 + nt * 8 + 2 * t);
            c2[nt].x = bb.x; c2[nt].y = bb.y;
            c2[nt].z = bb.x; c2[nt].w = bb.y;
        }
#pragma unroll
        for (int p = 0; p < 8; p++) {
            const int kb = p * 16;
            float a00 = phw[g * 132 + kb + t];
            float a01 = phw[(g + 8) * 132 + kb + t];
            float a02 = phw[g * 132 + kb + t + 4];
            float a03 = phw[(g + 8) * 132 + kb + t + 4];
            float a10 = phw[g * 132 + kb + t + 8];
            float a11 = phw[(g + 8) * 132 + kb + t + 8];
            float a12 = phw[g * 132 + kb + t + 12];
            float a13 = phw[(g + 8) * 132 + kb + t + 12];
            const float* bp = sm + E_W2Q + (p * 512 + lane) * 4;
#pragma unroll
            for (int nt = 0; nt < 16; nt++) {
                float4 b4 = *(const float4*)(bp + nt * 128);
                mma16n8k8(c2[nt], a00, a01, a02, a03, b4.x, b4.y);
                mma16n8k8(c2[nt], a10, a11, a12, a13, b4.z, b4.w);
            }
        }
        __syncwarp();   // all lanes done reading phi before overwrite

        // ---- pair-swap c2 into phi rows (bias already inside) ----
        {
            const int cq  = (t >> 1) * 4;
            const bool odd = (t & 1);
            const int row = g + (odd ? 8 : 0);
#pragma unroll
            for (int nt = 0; nt < 16; nt++) {
                float s0 = odd ? c2[nt].x : c2[nt].z;
                float s1 = odd ? c2[nt].y : c2[nt].w;
                float r0 = __shfl_xor_sync(0xffffffffu, s0, 1);
                float r1 = __shfl_xor_sync(0xffffffffu, s1, 1);
                float4 v;
                if (!odd) { v.x = c2[nt].x; v.y = c2[nt].y; v.z = r0; v.w = r1; }
                else      { v.x = r0; v.y = r1; v.z = c2[nt].z; v.w = c2[nt].w; }
                *(float4*)(phw + row * 132 + nt * 8 + cq) = v;
            }
        }
        __syncwarp();

        // ---- row-wise epilogue: one full h/agg row per warp-instr ----
#pragma unroll 4
        for (int el = 0; el < 16; el++) {
            float rc = __shfl_sync(0xffffffffu, rc_l, el);
            int   ji = __shfl_sync(0xffffffffu, ji_l, el);
            int   ii = __shfl_sync(0xffffffffu, ii_l, el);
            float4 v  = *(const float4*)(phw + el * 132 + lane * 4);
            float4 hv = *(const float4*)(g_h + (size_t)ji * NB + lane * 4);
            red_v4(g_agg + (size_t)ii * NB + lane * 4,
                   v.x * rc * hv.x, v.y * rc * hv.y,
                   v.z * rc * hv.z, v.w * rc * hv.w);
        }
        __syncwarp();
    }
}

// ======================= fused out kernel (tf32 mma, warp-decoupled) =======================
#define OW 8
#define OT (OW * 32)
#define O_W1P 0           // 16384
#define O_W2P 16384       // 16384
#define O_B1  32768
#define O_B2  32896
#define O_TILE 33024      // OW * 16*132 = 16896
#define O_SMEMF 49920
#define O_SMEMB (O_SMEMF * 4)
#define O_GRID 40

__global__ __launch_bounds__(OT, 1) void out_kernel(
    const float* __restrict__ A,     // g_agg
    const float* __restrict__ W1, const float* __restrict__ b1,
    const float* __restrict__ W2, const float* __restrict__ b2,
    float* __restrict__ out)
{
    extern __shared__ float sm[];
    const int tid  = threadIdx.x;
    const int warp = tid >> 5;
    const int lane = tid & 31;
    const int g    = lane >> 2;
    const int t    = lane & 3;

    for (int i = tid; i < 16 * 16 * 32; i += OT) {
        int ks = i >> 9, rem = i & 511, nt = rem >> 5, l = rem & 31;
        int gg = l >> 2, tt = l & 3;
        int k = ks * 8 + tt, n = nt * 8 + gg;
        sm[O_W1P + i * 2 + 0] = to_tf32(W1[k * NB + n]);
        sm[O_W1P + i * 2 + 1] = to_tf32(W1[(k + 4) * NB + n]);
        sm[O_W2P + i * 2 + 0] = to_tf32(W2[k * NB + n]);
        sm[O_W2P + i * 2 + 1] = to_tf32(W2[(k + 4) * NB + n]);
    }
    for (int i = tid; i < NB; i += OT) {
        sm[O_B1 + i] = b1[i];
        sm[O_B2 + i] = b2[i];
    }
    __syncthreads();

    float* tw = sm + O_TILE + warp * (16 * 132);
    const float4 b2v = *(const float4*)(sm + O_B2 + lane * 4);
    const int cq  = (t >> 1) * 4;
    const bool odd = (t & 1);
    const int srow = g + (odd ? 8 : 0);

    const int ngroups = N_ATOMS / 16;   // 1250 exact

    for (int grp = blockIdx.x * OW + warp; grp < ngroups; grp += gridDim.x * OW) {
        const int r0 = grp * 16;

#pragma unroll 4
        for (int el = 0; el < 16; el++) {
            float4 v = *(const float4*)(A + (size_t)(r0 + el) * NB + lane * 4);
            v.x = to_tf32(v.x); v.y = to_tf32(v.y);
            v.z = to_tf32(v.z); v.w = to_tf32(v.w);
            *(float4*)(tw + el * 132 + lane * 4) = v;
        }
        __syncwarp();

        // layer 1
        {
            float4 c1[16];
#pragma unroll
            for (int nt = 0; nt < 16; nt++) {
                float2 bb = *(const float2*)(sm + O_B1 + nt * 8 + 2 * t);
                c1[nt].x = bb.x; c1[nt].y = bb.y;
                c1[nt].z = bb.x; c1[nt].w = bb.y;
            }
            for (int ks = 0; ks < 16; ks++) {
                const int kb = ks * 8;
                float a0 = tw[g * 132 + kb + t];
                float a1 = tw[(g + 8) * 132 + kb + t];
                float a2 = tw[g * 132 + kb + t + 4];
                float a3 = tw[(g + 8) * 132 + kb + t + 4];
                const float* bp = sm + O_W1P + ((ks * 16) * 32 + lane) * 2;
#pragma unroll
                for (int nt = 0; nt < 16; nt++) {
                    float2 b = *(const float2*)(bp + nt * 64);
                    mma16n8k8(c1[nt], a0, a1, a2, a3, b.x, b.y);
                }
            }
            __syncwarp();
#pragma unroll
            for (int nt = 0; nt < 16; nt++) {
                float sx  = to_tf32(ssp_fast(c1[nt].x));
                float sy  = to_tf32(ssp_fast(c1[nt].y));
                float sz  = to_tf32(ssp_fast(c1[nt].z));
                float sw_ = to_tf32(ssp_fast(c1[nt].w));
                float s0 = odd ? sx : sz;
                float s1 = odd ? sy : sw_;
                float r0s = __shfl_xor_sync(0xffffffffu, s0, 1);
                float r1s = __shfl_xor_sync(0xffffffffu, s1, 1);
                float4 v;
                if (!odd) { v.x = sx;  v.y = sy;  v.z = r0s; v.w = r1s; }
                else      { v.x = r0s; v.y = r1s; v.z = sz;  v.w = sw_; }
                *(float4*)(tw + srow * 132 + nt * 8 + cq) = v;
            }
        }
        __syncwarp();

        // layer 2
        float4 c2[16];
#pragma unroll
        for (int nt = 0; nt < 16; nt++) c2[nt] = make_float4(0.f, 0.f, 0.f, 0.f);
        for (int ks = 0; ks < 16; ks++) {
            const int kb = ks * 8;
            float a0 = tw[g * 132 + kb + t];
            float a1 = tw[(g + 8) * 132 + kb + t];
            float a2 = tw[g * 132 + kb + t + 4];
            float a3 = tw[(g + 8) * 132 + kb + t + 4];
            const float* bp = sm + O_W2P + ((ks * 16) * 32 + lane) * 2;
#pragma unroll
            for (int nt = 0; nt < 16; nt++) {
                float2 b = *(const float2*)(bp + nt * 64);
                mma16n8k8(c2[nt], a0, a1, a2, a3, b.x, b.y);
            }
        }
        __syncwarp();

#pragma unroll
        for (int nt = 0; nt < 16; nt++) {
            float s0 = odd ? c2[nt].x : c2[nt].z;
            float s1 = odd ? c2[nt].y : c2[nt].w;
            float r0s = __shfl_xor_sync(0xffffffffu, s0, 1);
            float r1s = __shfl_xor_sync(0xffffffffu, s1, 1);
            float4 v;
            if (!odd) { v.x = c2[nt].x; v.y = c2[nt].y; v.z = r0s; v.w = r1s; }
            else      { v.x = r0s; v.y = r1s; v.z = c2[nt].z; v.w = c2[nt].w; }
            *(float4*)(tw + srow * 132 + nt * 8 + cq) = v;
        }
        __syncwarp();

#pragma unroll 4
        for (int el = 0; el < 16; el++) {
            float4 v = *(const float4*)(tw + el * 132 + lane * 4);
            v.x += b2v.x; v.y += b2v.y; v.z += b2v.z; v.w += b2v.w;
            *(float4*)(out + (size_t)(r0 + el) * NB + lane * 4) = v;
        }
        __syncwarp();
    }
}

extern "C" void kernel_launch(void* const* d_in, const int* in_sizes, int n_in,
                              void* d_out, int out_size)
{
    const float* x       = (const float*)d_in[0];
    const float* f_ij    = (const float*)d_in[1];
    const float* rcut_ij = (const float*)d_in[2];
    const int*   idx_i   = (const int*)d_in[3];
    const int*   idx_j   = (const int*)d_in[4];
    const float* W_in2f  = (const float*)d_in[5];
    const float* W_filt1 = (const float*)d_in[6];
    const float* b_filt1 = (const float*)d_in[7];
    const float* W_filt2 = (const float*)d_in[8];
    const float* b_filt2 = (const float*)d_in[9];
    const float* W_out1  = (const float*)d_in[10];
    const float* b_out1  = (const float*)d_in[11];
    const float* W_out2  = (const float*)d_in[12];
    const float* b_out2  = (const float*)d_in[13];
    float* out = (float*)d_out;

    void *p_h = nullptr, *p_agg = nullptr;
    cudaGetSymbolAddress(&p_h, g_h);
    cudaGetSymbolAddress(&p_agg, g_agg);
    float* h   = (float*)p_h;
    float* agg = (float*)p_agg;

    int nsm = 148;
    cudaDeviceGetAttribute(&nsm, cudaDevAttrMultiProcessorCount, 0);

    cudaFuncSetAttribute(edge_kernel,
                         cudaFuncAttributeMaxDynamicSharedMemorySize, E_SMEMB);
    cudaFuncSetAttribute(out_kernel,
                         cudaFuncAttributeMaxDynamicSharedMemorySize, O_SMEMB);

    // 1) zero accumulator
    {
        int n4 = (N_ATOMS * NB) / 4;
        zero_kernel<<<(n4 + 255) / 256, 256>>>((float4*)agg, n4);
    }
    // 2) h = x @ W_in2f (exact FFMA)
    gemm128_kernel<<<(N_ATOMS + 7) / 8, 128>>>(x, W_in2f, h, N_ATOMS);
    // 3) fused edge kernel
    edge_kernel<<<nsm, ET, E_SMEMB>>>(f_ij, rcut_ij, idx_i, idx_j,
                                      W_filt1, b_filt1, W_filt2, b_filt2);
    // 4+5) fused output MLP
    out_kernel<<<O_GRID, OT, O_SMEMB>>>(agg, W_out1, b_out1, W_out2, b_out2, out);
}

// round 11
// speedup vs baseline: 1.4453x; 1.4453x over previous
#include <cuda_runtime.h>
#include <cuda_fp16.h>
#include <cstdint>

// Problem constants
#define N_ATOMS 20000
#define N_EDGES 640000
#define NB      128
#define N_RBF   20

// -------- device scratch --------
__device__ float g_h[N_ATOMS * NB];
__device__ float g_agg[N_ATOMS * NB];

#define LN2F     0.69314718055994531f
#define LOG2EF   1.4426950408889634f
// softplus(x) - ln2 = max(x,0) + ln2*(lg2(1 + 2^(-|x|*log2e)) - 1)
__device__ __forceinline__ float ssp_fast(float x) {
    float u = fabsf(x) * -LOG2EF;
    float e; asm("ex2.approx.f32 %0, %1;" : "=f"(e) : "f"(u));
    float l; asm("lg2.approx.f32 %0, %1;" : "=f"(l) : "f"(1.0f + e));
    return fmaf(LN2F, l - 1.0f, fmaxf(x, 0.0f));
}

__device__ __forceinline__ uint32_t h2pack(float lo, float hi) {
    __half2 h = __floats2half2_rn(lo, hi);
    return *(uint32_t*)&h;
}

// m16n8k16 f16 mma, f32 accumulate (native HMMA shape, sm_80+)
__device__ __forceinline__ void mma_f16(float4& c,
                                        uint32_t a0, uint32_t a1, uint32_t a2, uint32_t a3,
                                        uint32_t b0, uint32_t b1) {
    asm volatile(
        "mma.sync.aligned.m16n8k16.row.col.f32.f16.f16.f32 "
        "{%0,%1,%2,%3}, {%4,%5,%6,%7}, {%8,%9}, {%0,%1,%2,%3};"
        : "+f"(c.x), "+f"(c.y), "+f"(c.z), "+f"(c.w)
        : "r"(a0), "r"(a1), "r"(a2), "r"(a3), "r"(b0), "r"(b1));
}

__device__ __forceinline__ void red_v4(float* p, float a, float b, float c, float d) {
    asm volatile("red.global.add.v4.f32 [%0], {%1, %2, %3, %4};"
                 :: "l"(p), "f"(a), "f"(b), "f"(c), "f"(d) : "memory");
}

// -------- zero kernel --------
__global__ void zero_kernel(float4* __restrict__ p, int n4) {
    int i = blockIdx.x * blockDim.x + threadIdx.x;
    if (i < n4) p[i] = make_float4(0.f, 0.f, 0.f, 0.f);
}

// -------- exact FFMA [rows,128]@[128,128] (h path), 8 rows/block --------
__global__ __launch_bounds__(128) void gemm128_kernel(
    const float* __restrict__ A, const float* __restrict__ W,
    float* __restrict__ C, int nrows)
{
    __shared__ float xs[8 * NB];
    const int row0 = blockIdx.x * 8;
    const int tid  = threadIdx.x;

    for (int i = tid; i < 8 * NB; i += 128) {
        int r = row0 + (i >> 7);
        xs[i] = (r < nrows) ? A[row0 * NB + i] : 0.0f;
    }
    __syncthreads();

    const int c = tid;
    float acc[8];
#pragma unroll
    for (int r = 0; r < 8; r++) acc[r] = 0.0f;

#pragma unroll 4
    for (int k = 0; k < NB; k++) {
        float w = W[k * NB + c];
#pragma unroll
        for (int r = 0; r < 8; r++) acc[r] += xs[r * NB + k] * w;
    }
#pragma unroll
    for (int r = 0; r < 8; r++) {
        int row = row0 + r;
        if (row < nrows) C[row * NB + c] = acc[r];
    }
}

// ======================= fused edge kernel (fp16 mma, warp-decoupled) =======================
// 12 warps/CTA. Per warp per 16-edge group:
//   layer1: c1(init=b1) += f@W1   (f16 m16n8k16, K pad 20->32, A direct from global)
//   fragment identity: layer-1 C maps lane-for-lane onto layer-2 A (after ssp+f16 pack)
//   layer2: c2(init=b2) += phi@W2 (f16 m16n8k16, K=128, LDS.128 feeds 2 mmas)
//   pair-swap c2 -> per-warp smem rows, row-wise epilogue (h gather + red.v4).
#define EW 12
#define ET (EW * 32)
// smem float-word offsets
#define E_W1F 0          // 2*16*32 uint2 = 2048 u32
#define E_W2F 2048       // 8*8*32 uint4  = 8192 u32
#define E_B1  10240      // 128
#define E_B2  10368      // 128
#define E_OUT 10496      // EW * 16*132 = 25344
#define E_SMEMF (10496 + EW * 2112)
#define E_SMEMB (E_SMEMF * 4)

__global__ __launch_bounds__(ET, 1) void edge_kernel(
    const float* __restrict__ f_ij, const float* __restrict__ rcut,
    const int* __restrict__ idx_i, const int* __restrict__ idx_j,
    const float* __restrict__ W1, const float* __restrict__ b1,
    const float* __restrict__ W2, const float* __restrict__ b2)
{
    extern __shared__ float sm[];
    const int tid  = threadIdx.x;
    const int warp = tid >> 5;
    const int lane = tid & 31;
    const int g    = lane >> 2;
    const int t    = lane & 3;

    // ---- stage W1 B-fragments (f16x2), [p1(2)][nt(16)][lane] x {b0,b1} ----
    for (int i = tid; i < 2 * 16 * 32; i += ET) {
        int p1 = i >> 9, nt = (i >> 5) & 15, l = i & 31;
        int gg = l >> 2, tt = l & 3;
        int n = nt * 8 + gg;
        int k0 = p1 * 16 + 2 * tt;
        float w00 = (k0     < N_RBF) ? W1[k0 * NB + n]       : 0.0f;
        float w01 = (k0 + 1 < N_RBF) ? W1[(k0 + 1) * NB + n] : 0.0f;
        float w10 = (k0 + 8 < N_RBF) ? W1[(k0 + 8) * NB + n] : 0.0f;
        float w11 = (k0 + 9 < N_RBF) ? W1[(k0 + 9) * NB + n] : 0.0f;
        uint2 v; v.x = h2pack(w00, w01); v.y = h2pack(w10, w11);
        ((uint2*)(sm + E_W1F))[i] = v;
    }
    // ---- stage W2 B-fragments, nt-paired: [p(8)][ntp(8)][lane] x {e0,e1,o0,o1} ----
    for (int i = tid; i < 8 * 8 * 32; i += ET) {
        int p = i >> 8, ntp = (i >> 5) & 7, l = i & 31;
        int gg = l >> 2, tt = l & 3;
        int k0 = p * 16 + 2 * tt;
        int nE = (2 * ntp) * 8 + gg, nO = nE + 8;
        uint4 v;
        v.x = h2pack(W2[k0 * NB + nE], W2[(k0 + 1) * NB + nE]);
        v.y = h2pack(W2[(k0 + 8) * NB + nE], W2[(k0 + 9) * NB + nE]);
        v.z = h2pack(W2[k0 * NB + nO], W2[(k0 + 1) * NB + nO]);
        v.w = h2pack(W2[(k0 + 8) * NB + nO], W2[(k0 + 9) * NB + nO]);
        ((uint4*)(sm + E_W2F))[i] = v;
    }
    for (int i = tid; i < NB; i += ET) {
        sm[E_B1 + i] = b1[i];
        sm[E_B2 + i] = b2[i];
    }
    __syncthreads();

    float* outw = sm + E_OUT + warp * 2112;   // 16 rows x 132 stride
    const int ngroups = N_EDGES / 16;          // 40000

    for (int grp = blockIdx.x * EW + warp; grp < ngroups; grp += gridDim.x * EW) {
        const int e0 = grp * 16;

        // edge metadata: lanes 0..15 hold one edge each
        float rc_l = 0.0f; int ji_l = 0, ii_l = 0;
        if (lane < 16) {
            rc_l = __ldg(rcut + e0 + lane);
            ji_l = __ldg(idx_j + e0 + lane);
            ii_l = __ldg(idx_i + e0 + lane);
        }

        // ---- layer 1 A fragments direct from global f (rows g, g+8) ----
        const float* fr0 = f_ij + (size_t)(e0 + g) * N_RBF;
        const float* fr1 = fr0 + 8 * N_RBF;
        float2 q00 = *(const float2*)(fr0 + 2 * t);       // cols 2t,2t+1   (<8)
        float2 q01 = *(const float2*)(fr1 + 2 * t);
        float2 q02 = *(const float2*)(fr0 + 2 * t + 8);   // cols 8..15
        float2 q03 = *(const float2*)(fr1 + 2 * t + 8);
        float2 q10 = make_float2(0.f, 0.f), q11 = make_float2(0.f, 0.f);
        if (t < 2) {                                       // cols 16..19; 20..23 pad
            q10 = *(const float2*)(fr0 + 2 * t + 16);
            q11 = *(const float2*)(fr1 + 2 * t + 16);
        }
        uint32_t A00 = h2pack(q00.x, q00.y), A01 = h2pack(q01.x, q01.y);
        uint32_t A02 = h2pack(q02.x, q02.y), A03 = h2pack(q03.x, q03.y);
        uint32_t A10 = h2pack(q10.x, q10.y), A11 = h2pack(q11.x, q11.y);

        // ---- layer 1: c1 = b1 + f @ W1 ----
        float4 c1[16];
#pragma unroll
        for (int nt = 0; nt < 16; nt++) {
            float2 bb = *(const float2*)(sm + E_B1 + nt * 8 + 2 * t);
            c1[nt].x = bb.x; c1[nt].y = bb.y;
            c1[nt].z = bb.x; c1[nt].w = bb.y;
        }
        {
            const uint2* w1p = (const uint2*)(sm + E_W1F) + lane;
#pragma unroll
            for (int nt = 0; nt < 16; nt++) {
                uint2 b0 = w1p[nt * 32];
                mma_f16(c1[nt], A00, A01, A02, A03, b0.x, b0.y);
                uint2 b1v = w1p[(16 + nt) * 32];
                mma_f16(c1[nt], A10, A11, 0u, 0u, b1v.x, b1v.y);
            }
        }

        // ---- fragment identity: ssp(c1) -> layer-2 A fragments (registers only) ----
        uint32_t paf[8][4];
#pragma unroll
        for (int p = 0; p < 8; p++) {
            paf[p][0] = h2pack(ssp_fast(c1[2 * p].x),     ssp_fast(c1[2 * p].y));
            paf[p][1] = h2pack(ssp_fast(c1[2 * p].z),     ssp_fast(c1[2 * p].w));
            paf[p][2] = h2pack(ssp_fast(c1[2 * p + 1].x), ssp_fast(c1[2 * p + 1].y));
            paf[p][3] = h2pack(ssp_fast(c1[2 * p + 1].z), ssp_fast(c1[2 * p + 1].w));
        }

        // ---- layer 2: c2 = b2 + phi @ W2 ----
        float4 c2[16];
#pragma unroll
        for (int nt = 0; nt < 16; nt++) {
            float2 bb = *(const float2*)(sm + E_B2 + nt * 8 + 2 * t);
            c2[nt].x = bb.x; c2[nt].y = bb.y;
            c2[nt].z = bb.x; c2[nt].w = bb.y;
        }
        {
            const uint4* w2p = (const uint4*)(sm + E_W2F) + lane;
#pragma unroll
            for (int p = 0; p < 8; p++) {
                uint32_t a0 = paf[p][0], a1 = paf[p][1], a2 = paf[p][2], a3 = paf[p][3];
#pragma unroll
                for (int ntp = 0; ntp < 8; ntp++) {
                    uint4 b = w2p[(p * 8 + ntp) * 32];
                    mma_f16(c2[2 * ntp],     a0, a1, a2, a3, b.x, b.y);
                    mma_f16(c2[2 * ntp + 1], a0, a1, a2, a3, b.z, b.w);
                }
            }
        }
        __syncwarp();   // outbuf from previous group fully consumed

        // ---- pair-swap c2 into per-warp rows (bias already inside) ----
        {
            const int cq  = (t >> 1) * 4;
            const bool odd = (t & 1);
            const int row = g + (odd ? 8 : 0);
#pragma unroll
            for (int nt = 0; nt < 16; nt++) {
                float s0 = odd ? c2[nt].x : c2[nt].z;
                float s1 = odd ? c2[nt].y : c2[nt].w;
                float r0 = __shfl_xor_sync(0xffffffffu, s0, 1);
                float r1 = __shfl_xor_sync(0xffffffffu, s1, 1);
                float4 v;
                if (!odd) { v.x = c2[nt].x; v.y = c2[nt].y; v.z = r0; v.w = r1; }
                else      { v.x = r0; v.y = r1; v.z = c2[nt].z; v.w = c2[nt].w; }
                *(float4*)(outw + row * 132 + nt * 8 + cq) = v;
            }
        }
        __syncwarp();

        // ---- row-wise epilogue: one full h/agg row per warp-instr ----
#pragma unroll 4
        for (int el = 0; el < 16; el++) {
            float rc = __shfl_sync(0xffffffffu, rc_l, el);
            int   ji = __shfl_sync(0xffffffffu, ji_l, el);
            int   ii = __shfl_sync(0xffffffffu, ii_l, el);
            float4 v  = *(const float4*)(outw + el * 132 + lane * 4);
            float4 hv = *(const float4*)(g_h + (size_t)ji * NB + lane * 4);
            red_v4(g_agg + (size_t)ii * NB + lane * 4,
                   v.x * rc * hv.x, v.y * rc * hv.y,
                   v.z * rc * hv.z, v.w * rc * hv.w);
        }
        __syncwarp();
    }
}

// ======================= fused out kernel (fp16 mma) =======================
#define OW 8
#define OT (OW * 32)
// smem float-word offsets
#define O_W1F 0          // 8*8*32 uint4 = 8192 u32
#define O_W2F 8192       // 8192
#define O_B1  16384
#define O_B2  16512
#define O_TILE 16640     // OW * 2112 = 16896
#define O_SMEMF (16640 + OW * 2112)
#define O_SMEMB (O_SMEMF * 4)

__global__ __launch_bounds__(OT, 1) void out_kernel(
    const float* __restrict__ A,     // g_agg
    const float* __restrict__ W1, const float* __restrict__ b1,
    const float* __restrict__ W2, const float* __restrict__ b2,
    float* __restrict__ out)
{
    extern __shared__ float sm[];
    const int tid  = threadIdx.x;
    const int warp = tid >> 5;
    const int lane = tid & 31;
    const int g    = lane >> 2;
    const int t    = lane & 3;

    // stage both weight B-fragment sets (nt-paired uint4 layout, K=128)
    for (int i = tid; i < 8 * 8 * 32; i += OT) {
        int p = i >> 8, ntp = (i >> 5) & 7, l = i & 31;
        int gg = l >> 2, tt = l & 3;
        int k0 = p * 16 + 2 * tt;
        int nE = (2 * ntp) * 8 + gg, nO = nE + 8;
        uint4 v1;
        v1.x = h2pack(W1[k0 * NB + nE], W1[(k0 + 1) * NB + nE]);
        v1.y = h2pack(W1[(k0 + 8) * NB + nE], W1[(k0 + 9) * NB + nE]);
        v1.z = h2pack(W1[k0 * NB + nO], W1[(k0 + 1) * NB + nO]);
        v1.w = h2pack(W1[(k0 + 8) * NB + nO], W1[(k0 + 9) * NB + nO]);
        ((uint4*)(sm + O_W1F))[i] = v1;
        uint4 v2;
        v2.x = h2pack(W2[k0 * NB + nE], W2[(k0 + 1) * NB + nE]);
        v2.y = h2pack(W2[(k0 + 8) * NB + nE], W2[(k0 + 9) * NB + nE]);
        v2.z = h2pack(W2[k0 * NB + nO], W2[(k0 + 1) * NB + nO]);
        v2.w = h2pack(W2[(k0 + 8) * NB + nO], W2[(k0 + 9) * NB + nO]);
        ((uint4*)(sm + O_W2F))[i] = v2;
    }
    for (int i = tid; i < NB; i += OT) {
        sm[O_B1 + i] = b1[i];
        sm[O_B2 + i] = b2[i];
    }
    __syncthreads();

    float* tw = sm + O_TILE + warp * 2112;
    const int ngroups = N_ATOMS / 16;   // 1250 exact

    for (int grp = blockIdx.x * OW + warp; grp < ngroups; grp += gridDim.x * OW) {
        const int r0 = grp * 16;

        // A fragments direct from agg (f32 -> f16)
        uint32_t af[8][4];
#pragma unroll
        for (int p = 0; p < 8; p++) {
            const float* r0p = A + (size_t)(r0 + g) * NB + p * 16;
            const float* r1p = r0p + 8 * NB;
            float2 x0 = *(const float2*)(r0p + 2 * t);
            float2 x1 = *(const float2*)(r1p + 2 * t);
            float2 x2 = *(const float2*)(r0p + 2 * t + 8);
            float2 x3 = *(const float2*)(r1p + 2 * t + 8);
            af[p][0] = h2pack(x0.x, x0.y);
            af[p][1] = h2pack(x1.x, x1.y);
            af[p][2] = h2pack(x2.x, x2.y);
            af[p][3] = h2pack(x3.x, x3.y);
        }

        // layer 1: c1 = b1 + A @ W1
        float4 c1[16];
#pragma unroll
        for (int nt = 0; nt < 16; nt++) {
            float2 bb = *(const float2*)(sm + O_B1 + nt * 8 + 2 * t);
            c1[nt].x = bb.x; c1[nt].y = bb.y;
            c1[nt].z = bb.x; c1[nt].w = bb.y;
        }
        {
            const uint4* wp = (const uint4*)(sm + O_W1F) + lane;
#pragma unroll
            for (int p = 0; p < 8; p++) {
                uint32_t a0 = af[p][0], a1 = af[p][1], a2 = af[p][2], a3 = af[p][3];
#pragma unroll
                for (int ntp = 0; ntp < 8; ntp++) {
                    uint4 b = wp[(p * 8 + ntp) * 32];
                    mma_f16(c1[2 * ntp],     a0, a1, a2, a3, b.x, b.y);
                    mma_f16(c1[2 * ntp + 1], a0, a1, a2, a3, b.z, b.w);
                }
            }
        }

        // fragment identity: ssp(c1) -> layer-2 A
        uint32_t paf[8][4];
#pragma unroll
        for (int p = 0; p < 8; p++) {
            paf[p][0] = h2pack(ssp_fast(c1[2 * p].x),     ssp_fast(c1[2 * p].y));
            paf[p][1] = h2pack(ssp_fast(c1[2 * p].z),     ssp_fast(c1[2 * p].w));
            paf[p][2] = h2pack(ssp_fast(c1[2 * p + 1].x), ssp_fast(c1[2 * p + 1].y));
            paf[p][3] = h2pack(ssp_fast(c1[2 * p + 1].z), ssp_fast(c1[2 * p + 1].w));
        }

        // layer 2: c2 = b2 + phi @ W2
        float4 c2[16];
#pragma unroll
        for (int nt = 0; nt < 16; nt++) {
            float2 bb = *(const float2*)(sm + O_B2 + nt * 8 + 2 * t);
            c2[nt].x = bb.x; c2[nt].y = bb.y;
            c2[nt].z = bb.x; c2[nt].w = bb.y;
        }
        {
            const uint4* wp = (const uint4*)(sm + O_W2F) + lane;
#pragma unroll
            for (int p = 0; p < 8; p++) {
                uint32_t a0 = paf[p][0], a1 = paf[p][1], a2 = paf[p][2], a3 = paf[p][3];
#pragma unroll
                for (int ntp = 0; ntp < 8; ntp++) {
                    uint4 b = wp[(p * 8 + ntp) * 32];
                    mma_f16(c2[2 * ntp],     a0, a1, a2, a3, b.x, b.y);
                    mma_f16(c2[2 * ntp + 1], a0, a1, a2, a3, b.z, b.w);
                }
            }
        }
        __syncwarp();

        // pair-swap -> tile rows (bias already inside)
        {
            const int cq  = (t >> 1) * 4;
            const bool odd = (t & 1);
            const int srow = g + (odd ? 8 : 0);
#pragma unroll
            for (int nt = 0; nt < 16; nt++) {
                float s0 = odd ? c2[nt].x : c2[nt].z;
                float s1 = odd ? c2[nt].y : c2[nt].w;
                float r0s = __shfl_xor_sync(0xffffffffu, s0, 1);
                float r1s = __shfl_xor_sync(0xffffffffu, s1, 1);
                float4 v;
                if (!odd) { v.x = c2[nt].x; v.y = c2[nt].y; v.z = r0s; v.w = r1s; }
                else      { v.x = r0s; v.y = r1s; v.z = c2[nt].z; v.w = c2[nt].w; }
                *(float4*)(tw + srow * 132 + nt * 8 + cq) = v;
            }
        }
        __syncwarp();

        // coalesced store: one full output row per warp-instr
#pragma unroll 4
        for (int el = 0; el < 16; el++) {
            float4 v = *(const float4*)(tw + el * 132 + lane * 4);
            *(float4*)(out + (size_t)(r0 + el) * NB + lane * 4) = v;
        }
        __syncwarp();
    }
}

extern "C" void kernel_launch(void* const* d_in, const int* in_sizes, int n_in,
                              void* d_out, int out_size)
{
    const float* x       = (const float*)d_in[0];
    const float* f_ij    = (const float*)d_in[1];
    const float* rcut_ij = (const float*)d_in[2];
    const int*   idx_i   = (const int*)d_in[3];
    const int*   idx_j   = (const int*)d_in[4];
    const float* W_in2f  = (const float*)d_in[5];
    const float* W_filt1 = (const float*)d_in[6];
    const float* b_filt1 = (const float*)d_in[7];
    const float* W_filt2 = (const float*)d_in[8];
    const float* b_filt2 = (const float*)d_in[9];
    const float* W_out1  = (const float*)d_in[10];
    const float* b_out1  = (const float*)d_in[11];
    const float* W_out2  = (const float*)d_in[12];
    const float* b_out2  = (const float*)d_in[13];
    float* out = (float*)d_out;

    void *p_h = nullptr, *p_agg = nullptr;
    cudaGetSymbolAddress(&p_h, g_h);
    cudaGetSymbolAddress(&p_agg, g_agg);
    float* h   = (float*)p_h;
    float* agg = (float*)p_agg;

    int nsm = 148;
    cudaDeviceGetAttribute(&nsm, cudaDevAttrMultiProcessorCount, 0);

    cudaFuncSetAttribute(edge_kernel,
                         cudaFuncAttributeMaxDynamicSharedMemorySize, E_SMEMB);
    cudaFuncSetAttribute(out_kernel,
                         cudaFuncAttributeMaxDynamicSharedMemorySize, O_SMEMB);

    // 1) zero accumulator
    {
        int n4 = (N_ATOMS * NB) / 4;
        zero_kernel<<<(n4 + 255) / 256, 256>>>((float4*)agg, n4);
    }
    // 2) h = x @ W_in2f (exact FFMA)
    gemm128_kernel<<<(N_ATOMS + 7) / 8, 128>>>(x, W_in2f, h, N_ATOMS);
    // 3) fused fp16-mma edge kernel
    edge_kernel<<<nsm, ET, E_SMEMB>>>(f_ij, rcut_ij, idx_i, idx_j,
                                      W_filt1, b_filt1, W_filt2, b_filt2);
    // 4+5) fused output MLP (full grid)
    out_kernel<<<nsm, OT, O_SMEMB>>>(agg, W_out1, b_out1, W_out2, b_out2, out);
}

// round 12
// speedup vs baseline: 1.6228x; 1.1228x over previous
#include <cuda_runtime.h>
#include <cuda_fp16.h>
#include <cstdint>

// Problem constants
#define N_ATOMS 20000
#define N_EDGES 640000
#define NB      128
#define N_RBF   20

// -------- device scratch --------
__device__ float g_h[N_ATOMS * NB];
__device__ float g_agg[N_ATOMS * NB];

#define LN2F     0.69314718055994531f
#define LOG2EF   1.4426950408889634f
// softplus(x) - ln2 = max(x,0) + ln2*(lg2(1 + 2^(-|x|*log2e)) - 1)
__device__ __forceinline__ float ssp_fast(float x) {
    float u = fabsf(x) * -LOG2EF;
    float e; asm("ex2.approx.f32 %0, %1;" : "=f"(e) : "f"(u));
    float l; asm("lg2.approx.f32 %0, %1;" : "=f"(l) : "f"(1.0f + e));
    return fmaf(LN2F, l - 1.0f, fmaxf(x, 0.0f));
}

__device__ __forceinline__ uint32_t h2pack(float lo, float hi) {
    __half2 h = __floats2half2_rn(lo, hi);
    return *(uint32_t*)&h;
}

// m16n8k16 f16 mma, f32 accumulate (native HMMA shape, sm_80+)
__device__ __forceinline__ void mma_f16(float4& c,
                                        uint32_t a0, uint32_t a1, uint32_t a2, uint32_t a3,
                                        uint32_t b0, uint32_t b1) {
    asm volatile(
        "mma.sync.aligned.m16n8k16.row.col.f32.f16.f16.f32 "
        "{%0,%1,%2,%3}, {%4,%5,%6,%7}, {%8,%9}, {%0,%1,%2,%3};"
        : "+f"(c.x), "+f"(c.y), "+f"(c.z), "+f"(c.w)
        : "r"(a0), "r"(a1), "r"(a2), "r"(a3), "r"(b0), "r"(b1));
}

__device__ __forceinline__ void red_v4(float* p, float a, float b, float c, float d) {
    asm volatile("red.global.add.v4.f32 [%0], {%1, %2, %3, %4};"
                 :: "l"(p), "f"(a), "f"(b), "f"(c), "f"(d) : "memory");
}

// ======================= h kernel (fp16 mma, 1 layer) + agg zeroing =======================
// h = x @ W_in2f ; also zeroes g_agg rows it covers (all rows, grid-stride exact).
#define HW 8
#define HT (HW * 32)
#define H_WF   0         // 8*8*32 uint4 = 8192 u32
#define H_TILE 8192      // HW * 2112 = 16896
#define H_SMEMF (8192 + HW * 2112)
#define H_SMEMB (H_SMEMF * 4)

__global__ __launch_bounds__(HT, 1) void h_kernel(
    const float* __restrict__ x, const float* __restrict__ W,
    float* __restrict__ h, float* __restrict__ agg)
{
    extern __shared__ float sm[];
    const int tid  = threadIdx.x;
    const int warp = tid >> 5;
    const int lane = tid & 31;
    const int g    = lane >> 2;
    const int t    = lane & 3;

    // stage W B-fragments (nt-paired uint4 layout, K=128)
    for (int i = tid; i < 8 * 8 * 32; i += HT) {
        int p = i >> 8, ntp = (i >> 5) & 7, l = i & 31;
        int gg = l >> 2, tt = l & 3;
        int k0 = p * 16 + 2 * tt;
        int nE = (2 * ntp) * 8 + gg, nO = nE + 8;
        uint4 v;
        v.x = h2pack(W[k0 * NB + nE], W[(k0 + 1) * NB + nE]);
        v.y = h2pack(W[(k0 + 8) * NB + nE], W[(k0 + 9) * NB + nE]);
        v.z = h2pack(W[k0 * NB + nO], W[(k0 + 1) * NB + nO]);
        v.w = h2pack(W[(k0 + 8) * NB + nO], W[(k0 + 9) * NB + nO]);
        ((uint4*)(sm + H_WF))[i] = v;
    }
    __syncthreads();

    float* tw = sm + H_TILE + warp * 2112;
    const int ngroups = N_ATOMS / 16;   // 1250 exact

    for (int grp = blockIdx.x * HW + warp; grp < ngroups; grp += gridDim.x * HW) {
        const int r0 = grp * 16;

        // A fragments direct from x (f32 -> f16)
        uint32_t af[8][4];
#pragma unroll
        for (int p = 0; p < 8; p++) {
            const float* r0p = x + (size_t)(r0 + g) * NB + p * 16;
            const float* r1p = r0p + 8 * NB;
            float2 x0 = *(const float2*)(r0p + 2 * t);
            float2 x1 = *(const float2*)(r1p + 2 * t);
            float2 x2 = *(const float2*)(r0p + 2 * t + 8);
            float2 x3 = *(const float2*)(r1p + 2 * t + 8);
            af[p][0] = h2pack(x0.x, x0.y);
            af[p][1] = h2pack(x1.x, x1.y);
            af[p][2] = h2pack(x2.x, x2.y);
            af[p][3] = h2pack(x3.x, x3.y);
        }

        float4 c[16];
#pragma unroll
        for (int nt = 0; nt < 16; nt++) c[nt] = make_float4(0.f, 0.f, 0.f, 0.f);
        {
            const uint4* wp = (const uint4*)(sm + H_WF) + lane;
#pragma unroll
            for (int p = 0; p < 8; p++) {
                uint32_t a0 = af[p][0], a1 = af[p][1], a2 = af[p][2], a3 = af[p][3];
#pragma unroll
                for (int ntp = 0; ntp < 8; ntp++) {
                    uint4 b = wp[(p * 8 + ntp) * 32];
                    mma_f16(c[2 * ntp],     a0, a1, a2, a3, b.x, b.y);
                    mma_f16(c[2 * ntp + 1], a0, a1, a2, a3, b.z, b.w);
                }
            }
        }
        __syncwarp();

        // pair-swap -> tile rows
        {
            const int cq  = (t >> 1) * 4;
            const bool odd = (t & 1);
            const int srow = g + (odd ? 8 : 0);
#pragma unroll
            for (int nt = 0; nt < 16; nt++) {
                float s0 = odd ? c[nt].x : c[nt].z;
                float s1 = odd ? c[nt].y : c[nt].w;
                float r0s = __shfl_xor_sync(0xffffffffu, s0, 1);
                float r1s = __shfl_xor_sync(0xffffffffu, s1, 1);
                float4 v;
                if (!odd) { v.x = c[nt].x; v.y = c[nt].y; v.z = r0s; v.w = r1s; }
                else      { v.x = r0s; v.y = r1s; v.z = c[nt].z; v.w = c[nt].w; }
                *(float4*)(tw + srow * 132 + nt * 8 + cq) = v;
            }
        }
        __syncwarp();

        // coalesced store h; zero agg rows
        const float4 z4 = make_float4(0.f, 0.f, 0.f, 0.f);
#pragma unroll 4
        for (int el = 0; el < 16; el++) {
            float4 v = *(const float4*)(tw + el * 132 + lane * 4);
            *(float4*)(h + (size_t)(r0 + el) * NB + lane * 4) = v;
            *(float4*)(agg + (size_t)(r0 + el) * NB + lane * 4) = z4;
        }
        __syncwarp();
    }
}

// ======================= fused edge kernel (fp16 mma, pipelined) =======================
// 12 warps/CTA. Per warp per 16-edge group (cross-iteration prefetch of f + metadata):
//   layer1: c1(init=b1) += f@W1   (f16 m16n8k16, K pad 20->32)
//   fragment identity: layer-1 C -> layer-2 A in registers (ssp + f16 pack)
//   layer2: c2(init=b2) += phi@W2
//   pair-swap c2 -> per-warp smem rows, row-wise epilogue (h gather + red.v4).
#define EW 12
#define ET (EW * 32)
// smem float-word offsets
#define E_W1F 0          // 2*16*32 uint2 = 2048 u32
#define E_W2F 2048       // 8*8*32 uint4  = 8192 u32
#define E_B1  10240      // 128
#define E_B2  10368      // 128
#define E_OUT 10496      // EW * 2112 = 25344
#define E_SMEMF (10496 + EW * 2112)
#define E_SMEMB (E_SMEMF * 4)

__global__ __launch_bounds__(ET, 1) void edge_kernel(
    const float* __restrict__ f_ij, const float* __restrict__ rcut,
    const int* __restrict__ idx_i, const int* __restrict__ idx_j,
    const float* __restrict__ W1, const float* __restrict__ b1,
    const float* __restrict__ W2, const float* __restrict__ b2)
{
    extern __shared__ float sm[];
    const int tid  = threadIdx.x;
    const int warp = tid >> 5;
    const int lane = tid & 31;
    const int g    = lane >> 2;
    const int t    = lane & 3;

    // ---- stage W1 B-fragments (f16x2), [p1(2)][nt(16)][lane] x {b0,b1} ----
    for (int i = tid; i < 2 * 16 * 32; i += ET) {
        int p1 = i >> 9, nt = (i >> 5) & 15, l = i & 31;
        int gg = l >> 2, tt = l & 3;
        int n = nt * 8 + gg;
        int k0 = p1 * 16 + 2 * tt;
        float w00 = (k0     < N_RBF) ? W1[k0 * NB + n]       : 0.0f;
        float w01 = (k0 + 1 < N_RBF) ? W1[(k0 + 1) * NB + n] : 0.0f;
        float w10 = (k0 + 8 < N_RBF) ? W1[(k0 + 8) * NB + n] : 0.0f;
        float w11 = (k0 + 9 < N_RBF) ? W1[(k0 + 9) * NB + n] : 0.0f;
        uint2 v; v.x = h2pack(w00, w01); v.y = h2pack(w10, w11);
        ((uint2*)(sm + E_W1F))[i] = v;
    }
    // ---- stage W2 B-fragments, nt-paired: [p(8)][ntp(8)][lane] x {e0,e1,o0,o1} ----
    for (int i = tid; i < 8 * 8 * 32; i += ET) {
        int p = i >> 8, ntp = (i >> 5) & 7, l = i & 31;
        int gg = l >> 2, tt = l & 3;
        int k0 = p * 16 + 2 * tt;
        int nE = (2 * ntp) * 8 + gg, nO = nE + 8;
        uint4 v;
        v.x = h2pack(W2[k0 * NB + nE], W2[(k0 + 1) * NB + nE]);
        v.y = h2pack(W2[(k0 + 8) * NB + nE], W2[(k0 + 9) * NB + nE]);
        v.z = h2pack(W2[k0 * NB + nO], W2[(k0 + 1) * NB + nO]);
        v.w = h2pack(W2[(k0 + 8) * NB + nO], W2[(k0 + 9) * NB + nO]);
        ((uint4*)(sm + E_W2F))[i] = v;
    }
    for (int i = tid; i < NB; i += ET) {
        sm[E_B1 + i] = b1[i];
        sm[E_B2 + i] = b2[i];
    }
    __syncthreads();

    float* outw = sm + E_OUT + warp * 2112;   // 16 rows x 132 stride
    const int ngroups = N_EDGES / 16;          // 40000
    const int gstride = gridDim.x * EW;

    // prefetch registers (raw, packed at use time)
    float2 q00, q01, q02, q03, q10, q11;
    float rcn = 0.0f; int jin = 0, iin = 0;

#define LOAD_GROUP(GIDX) do {                                              \
        const int _e0 = (GIDX) * 16;                                       \
        rcn = 0.0f; jin = 0; iin = 0;                                      \
        if (lane < 16) {                                                   \
            rcn = __ldg(rcut + _e0 + lane);                                \
            jin = __ldg(idx_j + _e0 + lane);                               \
            iin = __ldg(idx_i + _e0 + lane);                               \
        }                                                                  \
        const float* _fr0 = f_ij + (size_t)(_e0 + g) * N_RBF;              \
        const float* _fr1 = _fr0 + 8 * N_RBF;                              \
        q00 = *(const float2*)(_fr0 + 2 * t);                              \
        q01 = *(const float2*)(_fr1 + 2 * t);                              \
        q02 = *(const float2*)(_fr0 + 2 * t + 8);                          \
        q03 = *(const float2*)(_fr1 + 2 * t + 8);                          \
        q10 = make_float2(0.f, 0.f); q11 = make_float2(0.f, 0.f);          \
        if (t < 2) {                                                       \
            q10 = *(const float2*)(_fr0 + 2 * t + 16);                     \
            q11 = *(const float2*)(_fr1 + 2 * t + 16);                     \
        }                                                                  \
    } while (0)

    int grp = blockIdx.x * EW + warp;
    if (grp < ngroups) LOAD_GROUP(grp);

    while (grp < ngroups) {
        // consume prefetch: pack A fragments + copy metadata
        uint32_t A00 = h2pack(q00.x, q00.y), A01 = h2pack(q01.x, q01.y);
        uint32_t A02 = h2pack(q02.x, q02.y), A03 = h2pack(q03.x, q03.y);
        uint32_t A10 = h2pack(q10.x, q10.y), A11 = h2pack(q11.x, q11.y);
        float rc_l = rcn; int ji_l = jin, ii_l = iin;

        const int nxt = grp + gstride;
        if (nxt < ngroups) LOAD_GROUP(nxt);   // overlap with compute below

        // ---- layer 1: c1 = b1 + f @ W1 ----
        float4 c1[16];
#pragma unroll
        for (int nt = 0; nt < 16; nt++) {
            float2 bb = *(const float2*)(sm + E_B1 + nt * 8 + 2 * t);
            c1[nt].x = bb.x; c1[nt].y = bb.y;
            c1[nt].z = bb.x; c1[nt].w = bb.y;
        }
        {
            const uint2* w1p = (const uint2*)(sm + E_W1F) + lane;
#pragma unroll
            for (int nt = 0; nt < 16; nt++) {
                uint2 b0 = w1p[nt * 32];
                mma_f16(c1[nt], A00, A01, A02, A03, b0.x, b0.y);
                uint2 b1v = w1p[(16 + nt) * 32];
                mma_f16(c1[nt], A10, A11, 0u, 0u, b1v.x, b1v.y);
            }
        }

        // ---- fragment identity: ssp(c1) -> layer-2 A fragments (registers only) ----
        uint32_t paf[8][4];
#pragma unroll
        for (int p = 0; p < 8; p++) {
            paf[p][0] = h2pack(ssp_fast(c1[2 * p].x),     ssp_fast(c1[2 * p].y));
            paf[p][1] = h2pack(ssp_fast(c1[2 * p].z),     ssp_fast(c1[2 * p].w));
            paf[p][2] = h2pack(ssp_fast(c1[2 * p + 1].x), ssp_fast(c1[2 * p + 1].y));
            paf[p][3] = h2pack(ssp_fast(c1[2 * p + 1].z), ssp_fast(c1[2 * p + 1].w));
        }

        // ---- layer 2: c2 = b2 + phi @ W2 ----
        float4 c2[16];
#pragma unroll
        for (int nt = 0; nt < 16; nt++) {
            float2 bb = *(const float2*)(sm + E_B2 + nt * 8 + 2 * t);
            c2[nt].x = bb.x; c2[nt].y = bb.y;
            c2[nt].z = bb.x; c2[nt].w = bb.y;
        }
        {
            const uint4* w2p = (const uint4*)(sm + E_W2F) + lane;
#pragma unroll
            for (int p = 0; p < 8; p++) {
                uint32_t a0 = paf[p][0], a1 = paf[p][1], a2 = paf[p][2], a3 = paf[p][3];
#pragma unroll
                for (int ntp = 0; ntp < 8; ntp++) {
                    uint4 b = w2p[(p * 8 + ntp) * 32];
                    mma_f16(c2[2 * ntp],     a0, a1, a2, a3, b.x, b.y);
                    mma_f16(c2[2 * ntp + 1], a0, a1, a2, a3, b.z, b.w);
                }
            }
        }
        __syncwarp();   // outbuf from previous group fully consumed

        // ---- pair-swap c2 into per-warp rows (bias already inside) ----
        {
            const int cq  = (t >> 1) * 4;
            const bool odd = (t & 1);
            const int row = g + (odd ? 8 : 0);
#pragma unroll
            for (int nt = 0; nt < 16; nt++) {
                float s0 = odd ? c2[nt].x : c2[nt].z;
                float s1 = odd ? c2[nt].y : c2[nt].w;
                float r0 = __shfl_xor_sync(0xffffffffu, s0, 1);
                float r1 = __shfl_xor_sync(0xffffffffu, s1, 1);
                float4 v;
                if (!odd) { v.x = c2[nt].x; v.y = c2[nt].y; v.z = r0; v.w = r1; }
                else      { v.x = r0; v.y = r1; v.z = c2[nt].z; v.w = c2[nt].w; }
                *(float4*)(outw + row * 132 + nt * 8 + cq) = v;
            }
        }
        __syncwarp();

        // ---- row-wise epilogue: one full h/agg row per warp-instr ----
#pragma unroll 4
        for (int el = 0; el < 16; el++) {
            float rc = __shfl_sync(0xffffffffu, rc_l, el);
            int   ji = __shfl_sync(0xffffffffu, ji_l, el);
            int   ii = __shfl_sync(0xffffffffu, ii_l, el);
            float4 v  = *(const float4*)(outw + el * 132 + lane * 4);
            float4 hv = *(const float4*)(g_h + (size_t)ji * NB + lane * 4);
            red_v4(g_agg + (size_t)ii * NB + lane * 4,
                   v.x * rc * hv.x, v.y * rc * hv.y,
                   v.z * rc * hv.z, v.w * rc * hv.w);
        }
        __syncwarp();

        grp = nxt;
    }
#undef LOAD_GROUP
}

// ======================= fused out kernel (fp16 mma) =======================
#define OW 8
#define OT (OW * 32)
// smem float-word offsets
#define O_W1F 0          // 8*8*32 uint4 = 8192 u32
#define O_W2F 8192       // 8192
#define O_B1  16384
#define O_B2  16512
#define O_TILE 16640     // OW * 2112 = 16896
#define O_SMEMF (16640 + OW * 2112)
#define O_SMEMB (O_SMEMF * 4)

__global__ __launch_bounds__(OT, 1) void out_kernel(
    const float* __restrict__ A,     // g_agg
    const float* __restrict__ W1, const float* __restrict__ b1,
    const float* __restrict__ W2, const float* __restrict__ b2,
    float* __restrict__ out)
{
    extern __shared__ float sm[];
    const int tid  = threadIdx.x;
    const int warp = tid >> 5;
    const int lane = tid & 31;
    const int g    = lane >> 2;
    const int t    = lane & 3;

    // stage both weight B-fragment sets (nt-paired uint4 layout, K=128)
    for (int i = tid; i < 8 * 8 * 32; i += OT) {
        int p = i >> 8, ntp = (i >> 5) & 7, l = i & 31;
        int gg = l >> 2, tt = l & 3;
        int k0 = p * 16 + 2 * tt;
        int nE = (2 * ntp) * 8 + gg, nO = nE + 8;
        uint4 v1;
        v1.x = h2pack(W1[k0 * NB + nE], W1[(k0 + 1) * NB + nE]);
        v1.y = h2pack(W1[(k0 + 8) * NB + nE], W1[(k0 + 9) * NB + nE]);
        v1.z = h2pack(W1[k0 * NB + nO], W1[(k0 + 1) * NB + nO]);
        v1.w = h2pack(W1[(k0 + 8) * NB + nO], W1[(k0 + 9) * NB + nO]);
        ((uint4*)(sm + O_W1F))[i] = v1;
        uint4 v2;
        v2.x = h2pack(W2[k0 * NB + nE], W2[(k0 + 1) * NB + nE]);
        v2.y = h2pack(W2[(k0 + 8) * NB + nE], W2[(k0 + 9) * NB + nE]);
        v2.z = h2pack(W2[k0 * NB + nO], W2[(k0 + 1) * NB + nO]);
        v2.w = h2pack(W2[(k0 + 8) * NB + nO], W2[(k0 + 9) * NB + nO]);
        ((uint4*)(sm + O_W2F))[i] = v2;
    }
    for (int i = tid; i < NB; i += OT) {
        sm[O_B1 + i] = b1[i];
        sm[O_B2 + i] = b2[i];
    }
    __syncthreads();

    float* tw = sm + O_TILE + warp * 2112;
    const int ngroups = N_ATOMS / 16;   // 1250 exact

    for (int grp = blockIdx.x * OW + warp; grp < ngroups; grp += gridDim.x * OW) {
        const int r0 = grp * 16;

        // A fragments direct from agg (f32 -> f16)
        uint32_t af[8][4];
#pragma unroll
        for (int p = 0; p < 8; p++) {
            const float* r0p = A + (size_t)(r0 + g) * NB + p * 16;
            const float* r1p = r0p + 8 * NB;
            float2 x0 = *(const float2*)(r0p + 2 * t);
            float2 x1 = *(const float2*)(r1p + 2 * t);
            float2 x2 = *(const float2*)(r0p + 2 * t + 8);
            float2 x3 = *(const float2*)(r1p + 2 * t + 8);
            af[p][0] = h2pack(x0.x, x0.y);
            af[p][1] = h2pack(x1.x, x1.y);
            af[p][2] = h2pack(x2.x, x2.y);
            af[p][3] = h2pack(x3.x, x3.y);
        }

        // layer 1: c1 = b1 + A @ W1
        float4 c1[16];
#pragma unroll
        for (int nt = 0; nt < 16; nt++) {
            float2 bb = *(const float2*)(sm + O_B1 + nt * 8 + 2 * t);
            c1[nt].x = bb.x; c1[nt].y = bb.y;
            c1[nt].z = bb.x; c1[nt].w = bb.y;
        }
        {
            const uint4* wp = (const uint4*)(sm + O_W1F) + lane;
#pragma unroll
            for (int p = 0; p < 8; p++) {
                uint32_t a0 = af[p][0], a1 = af[p][1], a2 = af[p][2], a3 = af[p][3];
#pragma unroll
                for (int ntp = 0; ntp < 8; ntp++) {
                    uint4 b = wp[(p * 8 + ntp) * 32];
                    mma_f16(c1[2 * ntp],     a0, a1, a2, a3, b.x, b.y);
                    mma_f16(c1[2 * ntp + 1], a0, a1, a2, a3, b.z, b.w);
                }
            }
        }

        // fragment identity: ssp(c1) -> layer-2 A
        uint32_t paf[8][4];
#pragma unroll
        for (int p = 0; p < 8; p++) {
            paf[p][0] = h2pack(ssp_fast(c1[2 * p].x),     ssp_fast(c1[2 * p].y));
            paf[p][1] = h2pack(ssp_fast(c1[2 * p].z),     ssp_fast(c1[2 * p].w));
            paf[p][2] = h2pack(ssp_fast(c1[2 * p + 1].x), ssp_fast(c1[2 * p + 1].y));
            paf[p][3] = h2pack(ssp_fast(c1[2 * p + 1].z), ssp_fast(c1[2 * p + 1].w));
        }

        // layer 2: c2 = b2 + phi @ W2
        float4 c2[16];
#pragma unroll
        for (int nt = 0; nt < 16; nt++) {
            float2 bb = *(const float2*)(sm + O_B2 + nt * 8 + 2 * t);
            c2[nt].x = bb.x; c2[nt].y = bb.y;
            c2[nt].z = bb.x; c2[nt].w = bb.y;
        }
        {
            const uint4* wp = (const uint4*)(sm + O_W2F) + lane;
#pragma unroll
            for (int p = 0; p < 8; p++) {
                uint32_t a0 = paf[p][0], a1 = paf[p][1], a2 = paf[p][2], a3 = paf[p][3];
#pragma unroll
                for (int ntp = 0; ntp < 8; ntp++) {
                    uint4 b = wp[(p * 8 + ntp) * 32];
                    mma_f16(c2[2 * ntp],     a0, a1, a2, a3, b.x, b.y);
                    mma_f16(c2[2 * ntp + 1], a0, a1, a2, a3, b.z, b.w);
                }
            }
        }
        __syncwarp();

        // pair-swap -> tile rows (bias already inside)
        {
            const int cq  = (t >> 1) * 4;
            const bool odd = (t & 1);
            const int srow = g + (odd ? 8 : 0);
#pragma unroll
            for (int nt = 0; nt < 16; nt++) {
                float s0 = odd ? c2[nt].x : c2[nt].z;
                float s1 = odd ? c2[nt].y : c2[nt].w;
                float r0s = __shfl_xor_sync(0xffffffffu, s0, 1);
                float r1s = __shfl_xor_sync(0xffffffffu, s1, 1);
                float4 v;
                if (!odd) { v.x = c2[nt].x; v.y = c2[nt].y; v.z = r0s; v.w = r1s; }
                else      { v.x = r0s; v.y = r1s; v.z = c2[nt].z; v.w = c2[nt].w; }
                *(float4*)(tw + srow * 132 + nt * 8 + cq) = v;
            }
        }
        __syncwarp();

        // coalesced store: one full output row per warp-instr
#pragma unroll 4
        for (int el = 0; el < 16; el++) {
            float4 v = *(const float4*)(tw + el * 132 + lane * 4);
            *(float4*)(out + (size_t)(r0 + el) * NB + lane * 4) = v;
        }
        __syncwarp();
    }
}

extern "C" void kernel_launch(void* const* d_in, const int* in_sizes, int n_in,
                              void* d_out, int out_size)
{
    const float* x       = (const float*)d_in[0];
    const float* f_ij    = (const float*)d_in[1];
    const float* rcut_ij = (const float*)d_in[2];
    const int*   idx_i   = (const int*)d_in[3];
    const int*   idx_j   = (const int*)d_in[4];
    const float* W_in2f  = (const float*)d_in[5];
    const float* W_filt1 = (const float*)d_in[6];
    const float* b_filt1 = (const float*)d_in[7];
    const float* W_filt2 = (const float*)d_in[8];
    const float* b_filt2 = (const float*)d_in[9];
    const float* W_out1  = (const float*)d_in[10];
    const float* b_out1  = (const float*)d_in[11];
    const float* W_out2  = (const float*)d_in[12];
    const float* b_out2  = (const float*)d_in[13];
    float* out = (float*)d_out;

    void *p_h = nullptr, *p_agg = nullptr;
    cudaGetSymbolAddress(&p_h, g_h);
    cudaGetSymbolAddress(&p_agg, g_agg);
    float* h   = (float*)p_h;
    float* agg = (float*)p_agg;

    int nsm = 148;
    cudaDeviceGetAttribute(&nsm, cudaDevAttrMultiProcessorCount, 0);

    cudaFuncSetAttribute(h_kernel,
                         cudaFuncAttributeMaxDynamicSharedMemorySize, H_SMEMB);
    cudaFuncSetAttribute(edge_kernel,
                         cudaFuncAttributeMaxDynamicSharedMemorySize, E_SMEMB);
    cudaFuncSetAttribute(out_kernel,
                         cudaFuncAttributeMaxDynamicSharedMemorySize, O_SMEMB);

    // 1) h = x @ W_in2f (fp16 mma) + zero agg
    h_kernel<<<nsm, HT, H_SMEMB>>>(x, W_in2f, h, agg);
    // 2) fused fp16-mma edge kernel (pipelined)
    edge_kernel<<<nsm, ET, E_SMEMB>>>(f_ij, rcut_ij, idx_i, idx_j,
                                      W_filt1, b_filt1, W_filt2, b_filt2);
    // 3) fused output MLP
    out_kernel<<<nsm, OT, O_SMEMB>>>(agg, W_out1, b_out1, W_out2, b_out2, out);
}

// round 13
// speedup vs baseline: 1.6351x; 1.0076x over previous
#include <cuda_runtime.h>
#include <cuda_fp16.h>
#include <cstdint>

// Problem constants
#define N_ATOMS 20000
#define N_EDGES 640000
#define NB      128
#define N_RBF   20

// -------- device scratch --------
__device__ float g_h[N_ATOMS * NB];
__device__ float g_agg[N_ATOMS * NB];

#define LN2F     0.69314718055994531f
#define LOG2EF   1.4426950408889634f
// softplus(x) - ln2 = max(x,0) + ln2*(lg2(1 + 2^(-|x|*log2e)) - 1)
__device__ __forceinline__ float ssp_fast(float x) {
    float u = fabsf(x) * -LOG2EF;
    float e; asm("ex2.approx.f32 %0, %1;" : "=f"(e) : "f"(u));
    float l; asm("lg2.approx.f32 %0, %1;" : "=f"(l) : "f"(1.0f + e));
    return fmaf(LN2F, l - 1.0f, fmaxf(x, 0.0f));
}

__device__ __forceinline__ uint32_t h2pack(float lo, float hi) {
    __half2 h = __floats2half2_rn(lo, hi);
    return *(uint32_t*)&h;
}

// m16n8k16 f16 mma, f32 accumulate (native HMMA shape, sm_80+)
__device__ __forceinline__ void mma_f16(float4& c,
                                        uint32_t a0, uint32_t a1, uint32_t a2, uint32_t a3,
                                        uint32_t b0, uint32_t b1) {
    asm volatile(
        "mma.sync.aligned.m16n8k16.row.col.f32.f16.f16.f32 "
        "{%0,%1,%2,%3}, {%4,%5,%6,%7}, {%8,%9}, {%0,%1,%2,%3};"
        : "+f"(c.x), "+f"(c.y), "+f"(c.z), "+f"(c.w)
        : "r"(a0), "r"(a1), "r"(a2), "r"(a3), "r"(b0), "r"(b1));
}

__device__ __forceinline__ void red_v4(float* p, float a, float b, float c, float d) {
    asm volatile("red.global.add.v4.f32 [%0], {%1, %2, %3, %4};"
                 :: "l"(p), "f"(a), "f"(b), "f"(c), "f"(d) : "memory");
}

// ======================= h kernel (fp16 mma, 1 layer) + agg zeroing =======================
#define HW 8
#define HT (HW * 32)
#define H_WF   0         // 8*8*32 uint4 = 8192 u32
#define H_TILE 8192      // HW * 2112 = 16896
#define H_SMEMF (8192 + HW * 2112)
#define H_SMEMB (H_SMEMF * 4)

__global__ __launch_bounds__(HT, 1) void h_kernel(
    const float* __restrict__ x, const float* __restrict__ W,
    float* __restrict__ h, float* __restrict__ agg)
{
    extern __shared__ float sm[];
    const int tid  = threadIdx.x;
    const int warp = tid >> 5;
    const int lane = tid & 31;
    const int g    = lane >> 2;
    const int t    = lane & 3;

    for (int i = tid; i < 8 * 8 * 32; i += HT) {
        int p = i >> 8, ntp = (i >> 5) & 7, l = i & 31;
        int gg = l >> 2, tt = l & 3;
        int k0 = p * 16 + 2 * tt;
        int nE = (2 * ntp) * 8 + gg, nO = nE + 8;
        uint4 v;
        v.x = h2pack(W[k0 * NB + nE], W[(k0 + 1) * NB + nE]);
        v.y = h2pack(W[(k0 + 8) * NB + nE], W[(k0 + 9) * NB + nE]);
        v.z = h2pack(W[k0 * NB + nO], W[(k0 + 1) * NB + nO]);
        v.w = h2pack(W[(k0 + 8) * NB + nO], W[(k0 + 9) * NB + nO]);
        ((uint4*)(sm + H_WF))[i] = v;
    }
    __syncthreads();

    float* tw = sm + H_TILE + warp * 2112;
    const int ngroups = N_ATOMS / 16;   // 1250 exact

    for (int grp = blockIdx.x * HW + warp; grp < ngroups; grp += gridDim.x * HW) {
        const int r0 = grp * 16;

        uint32_t af[8][4];
#pragma unroll
        for (int p = 0; p < 8; p++) {
            const float* r0p = x + (size_t)(r0 + g) * NB + p * 16;
            const float* r1p = r0p + 8 * NB;
            float2 x0 = *(const float2*)(r0p + 2 * t);
            float2 x1 = *(const float2*)(r1p + 2 * t);
            float2 x2 = *(const float2*)(r0p + 2 * t + 8);
            float2 x3 = *(const float2*)(r1p + 2 * t + 8);
            af[p][0] = h2pack(x0.x, x0.y);
            af[p][1] = h2pack(x1.x, x1.y);
            af[p][2] = h2pack(x2.x, x2.y);
            af[p][3] = h2pack(x3.x, x3.y);
        }

        float4 c[16];
#pragma unroll
        for (int nt = 0; nt < 16; nt++) c[nt] = make_float4(0.f, 0.f, 0.f, 0.f);
        {
            const uint4* wp = (const uint4*)(sm + H_WF) + lane;
#pragma unroll
            for (int p = 0; p < 8; p++) {
                uint32_t a0 = af[p][0], a1 = af[p][1], a2 = af[p][2], a3 = af[p][3];
#pragma unroll
                for (int ntp = 0; ntp < 8; ntp++) {
                    uint4 b = wp[(p * 8 + ntp) * 32];
                    mma_f16(c[2 * ntp],     a0, a1, a2, a3, b.x, b.y);
                    mma_f16(c[2 * ntp + 1], a0, a1, a2, a3, b.z, b.w);
                }
            }
        }
        __syncwarp();

        {
            const int cq  = (t >> 1) * 4;
            const bool odd = (t & 1);
            const int srow = g + (odd ? 8 : 0);
#pragma unroll
            for (int nt = 0; nt < 16; nt++) {
                float s0 = odd ? c[nt].x : c[nt].z;
                float s1 = odd ? c[nt].y : c[nt].w;
                float r0s = __shfl_xor_sync(0xffffffffu, s0, 1);
                float r1s = __shfl_xor_sync(0xffffffffu, s1, 1);
                float4 v;
                if (!odd) { v.x = c[nt].x; v.y = c[nt].y; v.z = r0s; v.w = r1s; }
                else      { v.x = r0s; v.y = r1s; v.z = c[nt].z; v.w = c[nt].w; }
                *(float4*)(tw + srow * 132 + nt * 8 + cq) = v;
            }
        }
        __syncwarp();

        const float4 z4 = make_float4(0.f, 0.f, 0.f, 0.f);
#pragma unroll 4
        for (int el = 0; el < 16; el++) {
            float4 v = *(const float4*)(tw + el * 132 + lane * 4);
            *(float4*)(h + (size_t)(r0 + el) * NB + lane * 4) = v;
            *(float4*)(agg + (size_t)(r0 + el) * NB + lane * 4) = z4;
        }
        __syncwarp();
    }
}

// ======================= fused edge kernel (fp16 mma, 16 warps, split-half) ==============
// 16 warps/CTA (4/SMSP). Per warp per 16-edge group, register-halved phases:
//   layer1 (2 n-halves): c1[8] = b1 + f@W1 ; ssp -> paf incrementally
//   layer2 (2 n-halves): c2[8] = b2 + phi@W2 ; pair-swap half into smem rows
//   row-wise epilogue (h gather + red.v4).
#define EW 16
#define ET (EW * 32)
// smem float-word offsets
#define E_W1F 0          // 2*16*32 uint2 = 2048 u32
#define E_W2F 2048       // 8*8*32 uint4  = 8192 u32
#define E_B1  10240      // 128
#define E_B2  10368      // 128
#define E_OUT 10496      // EW * 2112 = 33792
#define E_SMEMF (10496 + EW * 2112)
#define E_SMEMB (E_SMEMF * 4)

__global__ __launch_bounds__(ET, 1) void edge_kernel(
    const float* __restrict__ f_ij, const float* __restrict__ rcut,
    const int* __restrict__ idx_i, const int* __restrict__ idx_j,
    const float* __restrict__ W1, const float* __restrict__ b1,
    const float* __restrict__ W2, const float* __restrict__ b2)
{
    extern __shared__ float sm[];
    const int tid  = threadIdx.x;
    const int warp = tid >> 5;
    const int lane = tid & 31;
    const int g    = lane >> 2;
    const int t    = lane & 3;

    // ---- stage W1 B-fragments (f16x2), [p1(2)][nt(16)][lane] x {b0,b1} ----
    for (int i = tid; i < 2 * 16 * 32; i += ET) {
        int p1 = i >> 9, nt = (i >> 5) & 15, l = i & 31;
        int gg = l >> 2, tt = l & 3;
        int n = nt * 8 + gg;
        int k0 = p1 * 16 + 2 * tt;
        float w00 = (k0     < N_RBF) ? W1[k0 * NB + n]       : 0.0f;
        float w01 = (k0 + 1 < N_RBF) ? W1[(k0 + 1) * NB + n] : 0.0f;
        float w10 = (k0 + 8 < N_RBF) ? W1[(k0 + 8) * NB + n] : 0.0f;
        float w11 = (k0 + 9 < N_RBF) ? W1[(k0 + 9) * NB + n] : 0.0f;
        uint2 v; v.x = h2pack(w00, w01); v.y = h2pack(w10, w11);
        ((uint2*)(sm + E_W1F))[i] = v;
    }
    // ---- stage W2 B-fragments, nt-paired: [p(8)][ntp(8)][lane] x {e0,e1,o0,o1} ----
    for (int i = tid; i < 8 * 8 * 32; i += ET) {
        int p = i >> 8, ntp = (i >> 5) & 7, l = i & 31;
        int gg = l >> 2, tt = l & 3;
        int k0 = p * 16 + 2 * tt;
        int nE = (2 * ntp) * 8 + gg, nO = nE + 8;
        uint4 v;
        v.x = h2pack(W2[k0 * NB + nE], W2[(k0 + 1) * NB + nE]);
        v.y = h2pack(W2[(k0 + 8) * NB + nE], W2[(k0 + 9) * NB + nE]);
        v.z = h2pack(W2[k0 * NB + nO], W2[(k0 + 1) * NB + nO]);
        v.w = h2pack(W2[(k0 + 8) * NB + nO], W2[(k0 + 9) * NB + nO]);
        ((uint4*)(sm + E_W2F))[i] = v;
    }
    for (int i = tid; i < NB; i += ET) {
        sm[E_B1 + i] = b1[i];
        sm[E_B2 + i] = b2[i];
    }
    __syncthreads();

    float* outw = sm + E_OUT + warp * 2112;   // 16 rows x 132 stride
    const int ngroups = N_EDGES / 16;          // 40000

    for (int grp = blockIdx.x * EW + warp; grp < ngroups; grp += gridDim.x * EW) {
        const int e0 = grp * 16;

        // edge metadata: lanes 0..15 hold one edge each
        float rc_l = 0.0f; int ji_l = 0, ii_l = 0;
        if (lane < 16) {
            rc_l = __ldg(rcut + e0 + lane);
            ji_l = __ldg(idx_j + e0 + lane);
            ii_l = __ldg(idx_i + e0 + lane);
        }

        // ---- layer 1 A fragments direct from global f (rows g, g+8) ----
        const float* fr0 = f_ij + (size_t)(e0 + g) * N_RBF;
        const float* fr1 = fr0 + 8 * N_RBF;
        float2 q00 = *(const float2*)(fr0 + 2 * t);       // cols 2t,2t+1   (<8)
        float2 q01 = *(const float2*)(fr1 + 2 * t);
        float2 q02 = *(const float2*)(fr0 + 2 * t + 8);   // cols 8..15
        float2 q03 = *(const float2*)(fr1 + 2 * t + 8);
        float2 q10 = make_float2(0.f, 0.f), q11 = make_float2(0.f, 0.f);
        if (t < 2) {                                       // cols 16..19; 20..23 pad
            q10 = *(const float2*)(fr0 + 2 * t + 16);
            q11 = *(const float2*)(fr1 + 2 * t + 16);
        }
        uint32_t A00 = h2pack(q00.x, q00.y), A01 = h2pack(q01.x, q01.y);
        uint32_t A02 = h2pack(q02.x, q02.y), A03 = h2pack(q03.x, q03.y);
        uint32_t A10 = h2pack(q10.x, q10.y), A11 = h2pack(q11.x, q11.y);

        // ---- layer 1 in two n-halves; build paf incrementally ----
        uint32_t paf[8][4];
#pragma unroll
        for (int hh = 0; hh < 2; hh++) {
            float4 c1[8];
#pragma unroll
            for (int j = 0; j < 8; j++) {
                float2 bb = *(const float2*)(sm + E_B1 + (8 * hh + j) * 8 + 2 * t);
                c1[j].x = bb.x; c1[j].y = bb.y;
                c1[j].z = bb.x; c1[j].w = bb.y;
            }
            const uint2* w1p = (const uint2*)(sm + E_W1F) + lane;
#pragma unroll
            for (int j = 0; j < 8; j++) {
                const int nt = 8 * hh + j;
                uint2 b0 = w1p[nt * 32];
                mma_f16(c1[j], A00, A01, A02, A03, b0.x, b0.y);
                uint2 b1v = w1p[(16 + nt) * 32];
                mma_f16(c1[j], A10, A11, 0u, 0u, b1v.x, b1v.y);
            }
#pragma unroll
            for (int j = 0; j < 4; j++) {
                const int p = 4 * hh + j;
                paf[p][0] = h2pack(ssp_fast(c1[2 * j].x),     ssp_fast(c1[2 * j].y));
                paf[p][1] = h2pack(ssp_fast(c1[2 * j].z),     ssp_fast(c1[2 * j].w));
                paf[p][2] = h2pack(ssp_fast(c1[2 * j + 1].x), ssp_fast(c1[2 * j + 1].y));
                paf[p][3] = h2pack(ssp_fast(c1[2 * j + 1].z), ssp_fast(c1[2 * j + 1].w));
            }
        }
        __syncwarp();   // previous group's outw fully consumed

        // ---- layer 2 in two n-halves; pair-swap each half into outw ----
        const int cq  = (t >> 1) * 4;
        const bool odd = (t & 1);
        const int row = g + (odd ? 8 : 0);
#pragma unroll
        for (int hh = 0; hh < 2; hh++) {
            float4 c2[8];
#pragma unroll
            for (int j = 0; j < 8; j++) {
                float2 bb = *(const float2*)(sm + E_B2 + (8 * hh + j) * 8 + 2 * t);
                c2[j].x = bb.x; c2[j].y = bb.y;
                c2[j].z = bb.x; c2[j].w = bb.y;
            }
            {
                const uint4* w2p = (const uint4*)(sm + E_W2F) + lane;
#pragma unroll
                for (int p = 0; p < 8; p++) {
                    uint32_t a0 = paf[p][0], a1 = paf[p][1];
                    uint32_t a2 = paf[p][2], a3 = paf[p][3];
#pragma unroll
                    for (int q = 0; q < 4; q++) {
                        const int ntp = 4 * hh + q;
                        uint4 b = w2p[(p * 8 + ntp) * 32];
                        mma_f16(c2[2 * q],     a0, a1, a2, a3, b.x, b.y);
                        mma_f16(c2[2 * q + 1], a0, a1, a2, a3, b.z, b.w);
                    }
                }
            }
            // pair-swap this half into outw
#pragma unroll
            for (int j = 0; j < 8; j++) {
                const int nt = 8 * hh + j;
                float s0 = odd ? c2[j].x : c2[j].z;
                float s1 = odd ? c2[j].y : c2[j].w;
                float r0 = __shfl_xor_sync(0xffffffffu, s0, 1);
                float r1 = __shfl_xor_sync(0xffffffffu, s1, 1);
                float4 v;
                if (!odd) { v.x = c2[j].x; v.y = c2[j].y; v.z = r0; v.w = r1; }
                else      { v.x = r0; v.y = r1; v.z = c2[j].z; v.w = c2[j].w; }
                *(float4*)(outw + row * 132 + nt * 8 + cq) = v;
            }
        }
        __syncwarp();

        // ---- row-wise epilogue: one full h/agg row per warp-instr ----
#pragma unroll 4
        for (int el = 0; el < 16; el++) {
            float rc = __shfl_sync(0xffffffffu, rc_l, el);
            int   ji = __shfl_sync(0xffffffffu, ji_l, el);
            int   ii = __shfl_sync(0xffffffffu, ii_l, el);
            float4 v  = *(const float4*)(outw + el * 132 + lane * 4);
            float4 hv = *(const float4*)(g_h + (size_t)ji * NB + lane * 4);
            red_v4(g_agg + (size_t)ii * NB + lane * 4,
                   v.x * rc * hv.x, v.y * rc * hv.y,
                   v.z * rc * hv.z, v.w * rc * hv.w);
        }
        __syncwarp();
    }
}

// ======================= fused out kernel (fp16 mma) =======================
#define OW 8
#define OT (OW * 32)
#define O_W1F 0          // 8*8*32 uint4 = 8192 u32
#define O_W2F 8192       // 8192
#define O_B1  16384
#define O_B2  16512
#define O_TILE 16640     // OW * 2112 = 16896
#define O_SMEMF (16640 + OW * 2112)
#define O_SMEMB (O_SMEMF * 4)

__global__ __launch_bounds__(OT, 1) void out_kernel(
    const float* __restrict__ A,     // g_agg
    const float* __restrict__ W1, const float* __restrict__ b1,
    const float* __restrict__ W2, const float* __restrict__ b2,
    float* __restrict__ out)
{
    extern __shared__ float sm[];
    const int tid  = threadIdx.x;
    const int warp = tid >> 5;
    const int lane = tid & 31;
    const int g    = lane >> 2;
    const int t    = lane & 3;

    for (int i = tid; i < 8 * 8 * 32; i += OT) {
        int p = i >> 8, ntp = (i >> 5) & 7, l = i & 31;
        int gg = l >> 2, tt = l & 3;
        int k0 = p * 16 + 2 * tt;
        int nE = (2 * ntp) * 8 + gg, nO = nE + 8;
        uint4 v1;
        v1.x = h2pack(W1[k0 * NB + nE], W1[(k0 + 1) * NB + nE]);
        v1.y = h2pack(W1[(k0 + 8) * NB + nE], W1[(k0 + 9) * NB + nE]);
        v1.z = h2pack(W1[k0 * NB + nO], W1[(k0 + 1) * NB + nO]);
        v1.w = h2pack(W1[(k0 + 8) * NB + nO], W1[(k0 + 9) * NB + nO]);
        ((uint4*)(sm + O_W1F))[i] = v1;
        uint4 v2;
        v2.x = h2pack(W2[k0 * NB + nE], W2[(k0 + 1) * NB + nE]);
        v2.y = h2pack(W2[(k0 + 8) * NB + nE], W2[(k0 + 9) * NB + nE]);
        v2.z = h2pack(W2[k0 * NB + nO], W2[(k0 + 1) * NB + nO]);
        v2.w = h2pack(W2[(k0 + 8) * NB + nO], W2[(k0 + 9) * NB + nO]);
        ((uint4*)(sm + O_W2F))[i] = v2;
    }
    for (int i = tid; i < NB; i += OT) {
        sm[O_B1 + i] = b1[i];
        sm[O_B2 + i] = b2[i];
    }
    __syncthreads();

    float* tw = sm + O_TILE + warp * 2112;
    const int ngroups = N_ATOMS / 16;   // 1250 exact

    for (int grp = blockIdx.x * OW + warp; grp < ngroups; grp += gridDim.x * OW) {
        const int r0 = grp * 16;

        uint32_t af[8][4];
#pragma unroll
        for (int p = 0; p < 8; p++) {
            const float* r0p = A + (size_t)(r0 + g) * NB + p * 16;
            const float* r1p = r0p + 8 * NB;
            float2 x0 = *(const float2*)(r0p + 2 * t);
            float2 x1 = *(const float2*)(r1p + 2 * t);
            float2 x2 = *(const float2*)(r0p + 2 * t + 8);
            float2 x3 = *(const float2*)(r1p + 2 * t + 8);
            af[p][0] = h2pack(x0.x, x0.y);
            af[p][1] = h2pack(x1.x, x1.y);
            af[p][2] = h2pack(x2.x, x2.y);
            af[p][3] = h2pack(x3.x, x3.y);
        }

        float4 c1[16];
#pragma unroll
        for (int nt = 0; nt < 16; nt++) {
            float2 bb = *(const float2*)(sm + O_B1 + nt * 8 + 2 * t);
            c1[nt].x = bb.x; c1[nt].y = bb.y;
            c1[nt].z = bb.x; c1[nt].w = bb.y;
        }
        {
            const uint4* wp = (const uint4*)(sm + O_W1F) + lane;
#pragma unroll
            for (int p = 0; p < 8; p++) {
                uint32_t a0 = af[p][0], a1 = af[p][1], a2 = af[p][2], a3 = af[p][3];
#pragma unroll
                for (int ntp = 0; ntp < 8; ntp++) {
                    uint4 b = wp[(p * 8 + ntp) * 32];
                    mma_f16(c1[2 * ntp],     a0, a1, a2, a3, b.x, b.y);
                    mma_f16(c1[2 * ntp + 1], a0, a1, a2, a3, b.z, b.w);
                }
            }
        }

        uint32_t paf[8][4];
#pragma unroll
        for (int p = 0; p < 8; p++) {
            paf[p][0] = h2pack(ssp_fast(c1[2 * p].x),     ssp_fast(c1[2 * p].y));
            paf[p][1] = h2pack(ssp_fast(c1[2 * p].z),     ssp_fast(c1[2 * p].w));
            paf[p][2] = h2pack(ssp_fast(c1[2 * p + 1].x), ssp_fast(c1[2 * p + 1].y));
            paf[p][3] = h2pack(ssp_fast(c1[2 * p + 1].z), ssp_fast(c1[2 * p + 1].w));
        }

        float4 c2[16];
#pragma unroll
        for (int nt = 0; nt < 16; nt++) {
            float2 bb = *(const float2*)(sm + O_B2 + nt * 8 + 2 * t);
            c2[nt].x = bb.x; c2[nt].y = bb.y;
            c2[nt].z = bb.x; c2[nt].w = bb.y;
        }
        {
            const uint4* wp = (const uint4*)(sm + O_W2F) + lane;
#pragma unroll
            for (int p = 0; p < 8; p++) {
                uint32_t a0 = paf[p][0], a1 = paf[p][1], a2 = paf[p][2], a3 = paf[p][3];
#pragma unroll
                for (int ntp = 0; ntp < 8; ntp++) {
                    uint4 b = wp[(p * 8 + ntp) * 32];
                    mma_f16(c2[2 * ntp],     a0, a1, a2, a3, b.x, b.y);
                    mma_f16(c2[2 * ntp + 1], a0, a1, a2, a3, b.z, b.w);
                }
            }
        }
        __syncwarp();

        {
            const int cq  = (t >> 1) * 4;
            const bool odd = (t & 1);
            const int srow = g + (odd ? 8 : 0);
#pragma unroll
            for (int nt = 0; nt < 16; nt++) {
                float s0 = odd ? c2[nt].x : c2[nt].z;
                float s1 = odd ? c2[nt].y : c2[nt].w;
                float r0s = __shfl_xor_sync(0xffffffffu, s0, 1);
                float r1s = __shfl_xor_sync(0xffffffffu, s1, 1);
                float4 v;
                if (!odd) { v.x = c2[nt].x; v.y = c2[nt].y; v.z = r0s; v.w = r1s; }
                else      { v.x = r0s; v.y = r1s; v.z = c2[nt].z; v.w = c2[nt].w; }
                *(float4*)(tw + srow * 132 + nt * 8 + cq) = v;
            }
        }
        __syncwarp();

#pragma unroll 4
        for (int el = 0; el < 16; el++) {
            float4 v = *(const float4*)(tw + el * 132 + lane * 4);
            *(float4*)(out + (size_t)(r0 + el) * NB + lane * 4) = v;
        }
        __syncwarp();
    }
}

extern "C" void kernel_launch(void* const* d_in, const int* in_sizes, int n_in,
                              void* d_out, int out_size)
{
    const float* x       = (const float*)d_in[0];
    const float* f_ij    = (const float*)d_in[1];
    const float* rcut_ij = (const float*)d_in[2];
    const int*   idx_i   = (const int*)d_in[3];
    const int*   idx_j   = (const int*)d_in[4];
    const float* W_in2f  = (const float*)d_in[5];
    const float* W_filt1 = (const float*)d_in[6];
    const float* b_filt1 = (const float*)d_in[7];
    const float* W_filt2 = (const float*)d_in[8];
    const float* b_filt2 = (const float*)d_in[9];
    const float* W_out1  = (const float*)d_in[10];
    const float* b_out1  = (const float*)d_in[11];
    const float* W_out2  = (const float*)d_in[12];
    const float* b_out2  = (const float*)d_in[13];
    float* out = (float*)d_out;

    void *p_h = nullptr, *p_agg = nullptr;
    cudaGetSymbolAddress(&p_h, g_h);
    cudaGetSymbolAddress(&p_agg, g_agg);
    float* h   = (float*)p_h;
    float* agg = (float*)p_agg;

    int nsm = 148;
    cudaDeviceGetAttribute(&nsm, cudaDevAttrMultiProcessorCount, 0);

    cudaFuncSetAttribute(h_kernel,
                         cudaFuncAttributeMaxDynamicSharedMemorySize, H_SMEMB);
    cudaFuncSetAttribute(edge_kernel,
                         cudaFuncAttributeMaxDynamicSharedMemorySize, E_SMEMB);
    cudaFuncSetAttribute(out_kernel,
                         cudaFuncAttributeMaxDynamicSharedMemorySize, O_SMEMB);

    // 1) h = x @ W_in2f (fp16 mma) + zero agg
    h_kernel<<<nsm, HT, H_SMEMB>>>(x, W_in2f, h, agg);
    // 2) fused fp16-mma edge kernel (16 warps, register-halved)
    edge_kernel<<<nsm, ET, E_SMEMB>>>(f_ij, rcut_ij, idx_i, idx_j,
                                      W_filt1, b_filt1, W_filt2, b_filt2);
    // 3) fused output MLP
    out_kernel<<<nsm, OT, O_SMEMB>>>(agg, W_out1, b_out1, W_out2, b_out2, out);
}

// round 14
// speedup vs baseline: 1.9027x; 1.1637x over previous
#include <cuda_runtime.h>
#include <cuda_fp16.h>
#include <cstdint>

// Problem constants
#define N_ATOMS 20000
#define N_EDGES 640000
#define NB      128
#define N_RBF   20

// -------- device scratch --------
__device__ __half g_hh[N_ATOMS * NB];      // h in fp16
__device__ float  g_agg[N_ATOMS * NB];
// packed weight fragments (filled by prep_kernel)
__device__ uint2 gPW1[2 * 16 * 32];        // edge layer1
__device__ uint4 gPW2[8 * 8 * 32];         // edge layer2 (nt-paired)
__device__ uint4 gPWH[8 * 8 * 32];         // h kernel W_in2f
__device__ uint4 gPO1[8 * 8 * 32];         // out layer1
__device__ uint4 gPO2[8 * 8 * 32];         // out layer2

#define LN2F     0.69314718055994531f
#define LOG2EF   1.4426950408889634f
__device__ __forceinline__ float ssp_fast(float x) {
    float u = fabsf(x) * -LOG2EF;
    float e; asm("ex2.approx.f32 %0, %1;" : "=f"(e) : "f"(u));
    float l; asm("lg2.approx.f32 %0, %1;" : "=f"(l) : "f"(1.0f + e));
    return fmaf(LN2F, l - 1.0f, fmaxf(x, 0.0f));
}

__device__ __forceinline__ uint32_t h2pack(float lo, float hi) {
    __half2 h = __floats2half2_rn(lo, hi);
    return *(uint32_t*)&h;
}
__device__ __forceinline__ float2 h2unpack(uint32_t u) {
    __half2 h = *(__half2*)&u;
    return __half22float2(h);
}

// m16n8k16 f16 mma, f32 accumulate
__device__ __forceinline__ void mma_f16(float4& c,
                                        uint32_t a0, uint32_t a1, uint32_t a2, uint32_t a3,
                                        uint32_t b0, uint32_t b1) {
    asm volatile(
        "mma.sync.aligned.m16n8k16.row.col.f32.f16.f16.f32 "
        "{%0,%1,%2,%3}, {%4,%5,%6,%7}, {%8,%9}, {%0,%1,%2,%3};"
        : "+f"(c.x), "+f"(c.y), "+f"(c.z), "+f"(c.w)
        : "r"(a0), "r"(a1), "r"(a2), "r"(a3), "r"(b0), "r"(b1));
}

__device__ __forceinline__ void red_v4(float* p, float a, float b, float c, float d) {
    asm volatile("red.global.add.v4.f32 [%0], {%1, %2, %3, %4};"
                 :: "l"(p), "f"(a), "f"(b), "f"(c), "f"(d) : "memory");
}

// ======================= prep kernel: pack weight fragments once =======================
__global__ void prep_kernel(const float* __restrict__ W1e, const float* __restrict__ W2e,
                            const float* __restrict__ Wh,  const float* __restrict__ Wo1,
                            const float* __restrict__ Wo2)
{
    const int tid = blockIdx.x * blockDim.x + threadIdx.x;
    const int stride = gridDim.x * blockDim.x;

    // edge layer1: [p1(2)][nt(16)][lane] x {b0,b1}
    for (int i = tid; i < 2 * 16 * 32; i += stride) {
        int p1 = i >> 9, nt = (i >> 5) & 15, l = i & 31;
        int gg = l >> 2, tt = l & 3;
        int n = nt * 8 + gg;
        int k0 = p1 * 16 + 2 * tt;
        float w00 = (k0     < N_RBF) ? W1e[k0 * NB + n]       : 0.0f;
        float w01 = (k0 + 1 < N_RBF) ? W1e[(k0 + 1) * NB + n] : 0.0f;
        float w10 = (k0 + 8 < N_RBF) ? W1e[(k0 + 8) * NB + n] : 0.0f;
        float w11 = (k0 + 9 < N_RBF) ? W1e[(k0 + 9) * NB + n] : 0.0f;
        uint2 v; v.x = h2pack(w00, w01); v.y = h2pack(w10, w11);
        gPW1[i] = v;
    }
    // nt-paired uint4 fragment sets: [p(8)][ntp(8)][lane]
    for (int i = tid; i < 8 * 8 * 32; i += stride) {
        int p = i >> 8, ntp = (i >> 5) & 7, l = i & 31;
        int gg = l >> 2, tt = l & 3;
        int k0 = p * 16 + 2 * tt;
        int nE = (2 * ntp) * 8 + gg, nO = nE + 8;
        uint4 v;
#define PACK4(W) do { \
        v.x = h2pack(W[k0 * NB + nE], W[(k0 + 1) * NB + nE]); \
        v.y = h2pack(W[(k0 + 8) * NB + nE], W[(k0 + 9) * NB + nE]); \
        v.z = h2pack(W[k0 * NB + nO], W[(k0 + 1) * NB + nO]); \
        v.w = h2pack(W[(k0 + 8) * NB + nO], W[(k0 + 9) * NB + nO]); } while (0)
        PACK4(W2e); gPW2[i] = v;
        PACK4(Wh);  gPWH[i] = v;
        PACK4(Wo1); gPO1[i] = v;
        PACK4(Wo2); gPO2[i] = v;
#undef PACK4
    }
}

// ======================= h kernel (fp16 mma) -> g_hh (half) + agg zeroing ================
#define HW 8
#define HT (HW * 32)
#define H_SMEMB (32768 + HW * 4224)

__global__ __launch_bounds__(HT, 1) void h_kernel(
    const float* __restrict__ x, float* __restrict__ agg)
{
    extern __shared__ char smc[];
    uint4* ws = (uint4*)smc;
    const int tid  = threadIdx.x;
    const int warp = tid >> 5;
    const int lane = tid & 31;
    const int g    = lane >> 2;
    const int t    = lane & 3;

    for (int i = tid; i < 2048; i += HT) ws[i] = gPWH[i];
    __syncthreads();

    __half* tw = (__half*)(smc + 32768 + warp * 4224);   // 16 rows x 132 halfs
    const int ngroups = N_ATOMS / 16;   // 1250

    for (int grp = blockIdx.x * HW + warp; grp < ngroups; grp += gridDim.x * HW) {
        const int r0 = grp * 16;

        uint32_t af[8][4];
#pragma unroll
        for (int p = 0; p < 8; p++) {
            const float* r0p = x + (size_t)(r0 + g) * NB + p * 16;
            const float* r1p = r0p + 8 * NB;
            float2 x0 = *(const float2*)(r0p + 2 * t);
            float2 x1 = *(const float2*)(r1p + 2 * t);
            float2 x2 = *(const float2*)(r0p + 2 * t + 8);
            float2 x3 = *(const float2*)(r1p + 2 * t + 8);
            af[p][0] = h2pack(x0.x, x0.y);
            af[p][1] = h2pack(x1.x, x1.y);
            af[p][2] = h2pack(x2.x, x2.y);
            af[p][3] = h2pack(x3.x, x3.y);
        }

        float4 c[16];
#pragma unroll
        for (int nt = 0; nt < 16; nt++) c[nt] = make_float4(0.f, 0.f, 0.f, 0.f);
#pragma unroll
        for (int p = 0; p < 8; p++) {
            uint32_t a0 = af[p][0], a1 = af[p][1], a2 = af[p][2], a3 = af[p][3];
#pragma unroll
            for (int ntp = 0; ntp < 8; ntp++) {
                uint4 b = ws[(p * 8 + ntp) * 32 + lane];
                mma_f16(c[2 * ntp],     a0, a1, a2, a3, b.x, b.y);
                mma_f16(c[2 * ntp + 1], a0, a1, a2, a3, b.z, b.w);
            }
        }
        __syncwarp();

        // pair-swap -> fp16 tile rows
        {
            const int cq  = (t >> 1) * 4;
            const bool odd = (t & 1);
            const int srow = g + (odd ? 8 : 0);
#pragma unroll
            for (int nt = 0; nt < 16; nt++) {
                float s0 = odd ? c[nt].x : c[nt].z;
                float s1 = odd ? c[nt].y : c[nt].w;
                float r0s = __shfl_xor_sync(0xffffffffu, s0, 1);
                float r1s = __shfl_xor_sync(0xffffffffu, s1, 1);
                float4 v;
                if (!odd) { v.x = c[nt].x; v.y = c[nt].y; v.z = r0s; v.w = r1s; }
                else      { v.x = r0s; v.y = r1s; v.z = c[nt].z; v.w = c[nt].w; }
                uint2 pk; pk.x = h2pack(v.x, v.y); pk.y = h2pack(v.z, v.w);
                *(uint2*)(tw + srow * 132 + nt * 8 + cq) = pk;
            }
        }
        __syncwarp();

        // coalesced half row store + agg zero
        const float4 z4 = make_float4(0.f, 0.f, 0.f, 0.f);
#pragma unroll 4
        for (int el = 0; el < 16; el++) {
            uint2 v = *(const uint2*)(tw + el * 132 + lane * 4);
            ((uint2*)(g_hh + (size_t)(r0 + el) * NB))[lane] = v;
            *(float4*)(agg + (size_t)(r0 + el) * NB + lane * 4) = z4;
        }
        __syncwarp();
    }
}

// ======================= fused edge kernel (M=32 per warp, fp16 tiles) ==================
#define EW 12
#define ET (EW * 32)
// smem bytes: [0,8192) W1 uint2[1024]; [8192,40960) W2 uint4[2048];
// [40960,41472) b1 f32[128]; [41472,..) outw per warp: half[32*132] = 8448B
#define E_OUTB 41472
#define E_SMEMB (E_OUTB + EW * 8448)

__global__ __launch_bounds__(ET, 1) void edge_kernel(
    const float* __restrict__ f_ij, const float* __restrict__ rcut,
    const int* __restrict__ idx_i, const int* __restrict__ idx_j,
    const float* __restrict__ b1, const float* __restrict__ b2)
{
    extern __shared__ char smc[];
    uint2* w1s = (uint2*)smc;
    uint4* w2s = (uint4*)(smc + 8192);
    float* b1s = (float*)(smc + 40960);
    const int tid  = threadIdx.x;
    const int warp = tid >> 5;
    const int lane = tid & 31;
    const int g    = lane >> 2;
    const int t    = lane & 3;

    for (int i = tid; i < 1024; i += ET) w1s[i] = gPW1[i];
    for (int i = tid; i < 2048; i += ET) w2s[i] = gPW2[i];
    for (int i = tid; i < NB; i += ET) b1s[i] = b1[i];
    __syncthreads();

    __half* outw = (__half*)(smc + E_OUTB + warp * 8448);  // 32 rows x 132 halfs
    const float4 b2v = *(const float4*)(b2 + lane * 4);
    const int cq  = (t >> 1) * 4;
    const bool odd = (t & 1);
    const int ngroups = N_EDGES / 32;  // 20000

    for (int grp = blockIdx.x * EW + warp; grp < ngroups; grp += gridDim.x * EW) {
        const int e0 = grp * 32;

        // metadata: all 32 lanes hold one edge each
        const float rc_l = __ldg(rcut + e0 + lane);
        const int   ji_l = __ldg(idx_j + e0 + lane);
        const int   ii_l = __ldg(idx_i + e0 + lane);

        // layer-1 A fragments for both 16-edge subsets
        uint32_t A[2][6];
#pragma unroll
        for (int s = 0; s < 2; s++) {
            const float* fr0 = f_ij + (size_t)(e0 + 16 * s + g) * N_RBF;
            const float* fr1 = fr0 + 8 * N_RBF;
            float2 q00 = *(const float2*)(fr0 + 2 * t);
            float2 q01 = *(const float2*)(fr1 + 2 * t);
            float2 q02 = *(const float2*)(fr0 + 2 * t + 8);
            float2 q03 = *(const float2*)(fr1 + 2 * t + 8);
            float2 q10 = make_float2(0.f, 0.f), q11 = make_float2(0.f, 0.f);
            if (t < 2) {
                q10 = *(const float2*)(fr0 + 2 * t + 16);
                q11 = *(const float2*)(fr1 + 2 * t + 16);
            }
            A[s][0] = h2pack(q00.x, q00.y); A[s][1] = h2pack(q01.x, q01.y);
            A[s][2] = h2pack(q02.x, q02.y); A[s][3] = h2pack(q03.x, q03.y);
            A[s][4] = h2pack(q10.x, q10.y); A[s][5] = h2pack(q11.x, q11.y);
        }

        // ---- layer 1 in quarters (4 nt each), both subsets share B loads ----
        uint32_t paf[2][8][4];
#pragma unroll
        for (int qt = 0; qt < 4; qt++) {
            float4 c1[2][4];
#pragma unroll
            for (int j = 0; j < 4; j++) {
                float2 bb = *(const float2*)(b1s + (4 * qt + j) * 8 + 2 * t);
#pragma unroll
                for (int s = 0; s < 2; s++) {
                    c1[s][j].x = bb.x; c1[s][j].y = bb.y;
                    c1[s][j].z = bb.x; c1[s][j].w = bb.y;
                }
            }
#pragma unroll
            for (int j = 0; j < 4; j++) {
                const int nt = 4 * qt + j;
                uint2 b0  = w1s[nt * 32 + lane];
                uint2 b1f = w1s[(16 + nt) * 32 + lane];
#pragma unroll
                for (int s = 0; s < 2; s++) {
                    mma_f16(c1[s][j], A[s][0], A[s][1], A[s][2], A[s][3], b0.x, b0.y);
                    mma_f16(c1[s][j], A[s][4], A[s][5], 0u, 0u, b1f.x, b1f.y);
                }
            }
#pragma unroll
            for (int s = 0; s < 2; s++)
#pragma unroll
                for (int jj = 0; jj < 2; jj++) {
                    const int p = 2 * qt + jj;
                    paf[s][p][0] = h2pack(ssp_fast(c1[s][2 * jj].x),     ssp_fast(c1[s][2 * jj].y));
                    paf[s][p][1] = h2pack(ssp_fast(c1[s][2 * jj].z),     ssp_fast(c1[s][2 * jj].w));
                    paf[s][p][2] = h2pack(ssp_fast(c1[s][2 * jj + 1].x), ssp_fast(c1[s][2 * jj + 1].y));
                    paf[s][p][3] = h2pack(ssp_fast(c1[s][2 * jj + 1].z), ssp_fast(c1[s][2 * jj + 1].w));
                }
        }
        __syncwarp();   // previous group's outw fully consumed before overwrite

        // ---- layer 2 in quarters; pair-swap each quarter to fp16 outw ----
#pragma unroll
        for (int qt = 0; qt < 4; qt++) {
            float4 c2[2][4];
#pragma unroll
            for (int s = 0; s < 2; s++)
#pragma unroll
                for (int j = 0; j < 4; j++) c2[s][j] = make_float4(0.f, 0.f, 0.f, 0.f);
#pragma unroll
            for (int p = 0; p < 8; p++) {
#pragma unroll
                for (int jj = 0; jj < 2; jj++) {
                    const int ntp = 2 * qt + jj;
                    uint4 b = w2s[(p * 8 + ntp) * 32 + lane];
#pragma unroll
                    for (int s = 0; s < 2; s++) {
                        mma_f16(c2[s][2 * jj],     paf[s][p][0], paf[s][p][1],
                                paf[s][p][2], paf[s][p][3], b.x, b.y);
                        mma_f16(c2[s][2 * jj + 1], paf[s][p][0], paf[s][p][1],
                                paf[s][p][2], paf[s][p][3], b.z, b.w);
                    }
                }
            }
            // pair-swap this quarter into outw (fp16)
#pragma unroll
            for (int s = 0; s < 2; s++) {
                const int row = 16 * s + g + (odd ? 8 : 0);
#pragma unroll
                for (int j = 0; j < 4; j++) {
                    const int nt = 4 * qt + j;
                    float s0 = odd ? c2[s][j].x : c2[s][j].z;
                    float s1 = odd ? c2[s][j].y : c2[s][j].w;
                    float r0 = __shfl_xor_sync(0xffffffffu, s0, 1);
                    float r1 = __shfl_xor_sync(0xffffffffu, s1, 1);
                    float4 v;
                    if (!odd) { v.x = c2[s][j].x; v.y = c2[s][j].y; v.z = r0; v.w = r1; }
                    else      { v.x = r0; v.y = r1; v.z = c2[s][j].z; v.w = c2[s][j].w; }
                    uint2 pk; pk.x = h2pack(v.x, v.y); pk.y = h2pack(v.z, v.w);
                    *(uint2*)(outw + row * 132 + nt * 8 + cq) = pk;
                }
            }
        }
        __syncwarp();

        // ---- row-wise epilogue: 32 edges, one full row per warp-instr ----
#pragma unroll 4
        for (int el = 0; el < 32; el++) {
            float rc = __shfl_sync(0xffffffffu, rc_l, el);
            int   ji = __shfl_sync(0xffffffffu, ji_l, el);
            int   ii = __shfl_sync(0xffffffffu, ii_l, el);
            uint2 pv = *(const uint2*)(outw + el * 132 + lane * 4);
            float2 f0 = h2unpack(pv.x), f1 = h2unpack(pv.y);
            uint2 ph = __ldg((const uint2*)(g_hh + (size_t)ji * NB) + lane);
            float2 g0 = h2unpack(ph.x), g1 = h2unpack(ph.y);
            red_v4(g_agg + (size_t)ii * NB + lane * 4,
                   (f0.x + b2v.x) * rc * g0.x,
                   (f0.y + b2v.y) * rc * g0.y,
                   (f1.x + b2v.z) * rc * g1.x,
                   (f1.y + b2v.w) * rc * g1.y);
        }
        __syncwarp();
    }
}

// ======================= fused out kernel (fp16 mma) =======================
#define OW 8
#define OT (OW * 32)
// smem bytes: [0,32768) O1; [32768,65536) O2; [65536,66048) b1; [66048,66560) b2;
// tw per warp f32[2112] at 66560
#define O_TWB 66560
#define O_SMEMB (O_TWB + OW * 8448)

__global__ __launch_bounds__(OT, 1) void out_kernel(
    const float* __restrict__ A,     // g_agg
    const float* __restrict__ b1, const float* __restrict__ b2,
    float* __restrict__ out)
{
    extern __shared__ char smc[];
    uint4* w1s = (uint4*)smc;
    uint4* w2s = (uint4*)(smc + 32768);
    float* b1s = (float*)(smc + 65536);
    float* b2s = (float*)(smc + 66048);
    const int tid  = threadIdx.x;
    const int warp = tid >> 5;
    const int lane = tid & 31;
    const int g    = lane >> 2;
    const int t    = lane & 3;

    for (int i = tid; i < 2048; i += OT) { w1s[i] = gPO1[i]; w2s[i] = gPO2[i]; }
    for (int i = tid; i < NB; i += OT) { b1s[i] = b1[i]; b2s[i] = b2[i]; }
    __syncthreads();

    float* tw = (float*)(smc + O_TWB + warp * 8448);
    const int ngroups = N_ATOMS / 16;   // 1250

    for (int grp = blockIdx.x * OW + warp; grp < ngroups; grp += gridDim.x * OW) {
        const int r0 = grp * 16;

        uint32_t af[8][4];
#pragma unroll
        for (int p = 0; p < 8; p++) {
            const float* r0p = A + (size_t)(r0 + g) * NB + p * 16;
            const float* r1p = r0p + 8 * NB;
            float2 x0 = *(const float2*)(r0p + 2 * t);
            float2 x1 = *(const float2*)(r1p + 2 * t);
            float2 x2 = *(const float2*)(r0p + 2 * t + 8);
            float2 x3 = *(const float2*)(r1p + 2 * t + 8);
            af[p][0] = h2pack(x0.x, x0.y);
            af[p][1] = h2pack(x1.x, x1.y);
            af[p][2] = h2pack(x2.x, x2.y);
            af[p][3] = h2pack(x3.x, x3.y);
        }

        float4 c1[16];
#pragma unroll
        for (int nt = 0; nt < 16; nt++) {
            float2 bb = *(const float2*)(b1s + nt * 8 + 2 * t);
            c1[nt].x = bb.x; c1[nt].y = bb.y;
            c1[nt].z = bb.x; c1[nt].w = bb.y;
        }
#pragma unroll
        for (int p = 0; p < 8; p++) {
            uint32_t a0 = af[p][0], a1 = af[p][1], a2 = af[p][2], a3 = af[p][3];
#pragma unroll
            for (int ntp = 0; ntp < 8; ntp++) {
                uint4 b = w1s[(p * 8 + ntp) * 32 + lane];
                mma_f16(c1[2 * ntp],     a0, a1, a2, a3, b.x, b.y);
                mma_f16(c1[2 * ntp + 1], a0, a1, a2, a3, b.z, b.w);
            }
        }

        uint32_t paf[8][4];
#pragma unroll
        for (int p = 0; p < 8; p++) {
            paf[p][0] = h2pack(ssp_fast(c1[2 * p].x),     ssp_fast(c1[2 * p].y));
            paf[p][1] = h2pack(ssp_fast(c1[2 * p].z),     ssp_fast(c1[2 * p].w));
            paf[p][2] = h2pack(ssp_fast(c1[2 * p + 1].x), ssp_fast(c1[2 * p + 1].y));
            paf[p][3] = h2pack(ssp_fast(c1[2 * p + 1].z), ssp_fast(c1[2 * p + 1].w));
        }

        float4 c2[16];
#pragma unroll
        for (int nt = 0; nt < 16; nt++) {
            float2 bb = *(const float2*)(b2s + nt * 8 + 2 * t);
            c2[nt].x = bb.x; c2[nt].y = bb.y;
            c2[nt].z = bb.x; c2[nt].w = bb.y;
        }
#pragma unroll
        for (int p = 0; p < 8; p++) {
            uint32_t a0 = paf[p][0], a1 = paf[p][1], a2 = paf[p][2], a3 = paf[p][3];
#pragma unroll
            for (int ntp = 0; ntp < 8; ntp++) {
                uint4 b = w2s[(p * 8 + ntp) * 32 + lane];
                mma_f16(c2[2 * ntp],     a0, a1, a2, a3, b.x, b.y);
                mma_f16(c2[2 * ntp + 1], a0, a1, a2, a3, b.z, b.w);
            }
        }
        __syncwarp();

        {
            const int cq  = (t >> 1) * 4;
            const bool odd = (t & 1);
            const int srow = g + (odd ? 8 : 0);
#pragma unroll
            for (int nt = 0; nt < 16; nt++) {
                float s0 = odd ? c2[nt].x : c2[nt].z;
                float s1 = odd ? c2[nt].y : c2[nt].w;
                float r0s = __shfl_xor_sync(0xffffffffu, s0, 1);
                float r1s = __shfl_xor_sync(0xffffffffu, s1, 1);
                float4 v;
                if (!odd) { v.x = c2[nt].x; v.y = c2[nt].y; v.z = r0s; v.w = r1s; }
                else      { v.x = r0s; v.y = r1s; v.z = c2[nt].z; v.w = c2[nt].w; }
                *(float4*)(tw + srow * 132 + nt * 8 + cq) = v;
            }
        }
        __syncwarp();

#pragma unroll 4
        for (int el = 0; el < 16; el++) {
            float4 v = *(const float4*)(tw + el * 132 + lane * 4);
            *(float4*)(out + (size_t)(r0 + el) * NB + lane * 4) = v;
        }
        __syncwarp();
    }
}

extern "C" void kernel_launch(void* const* d_in, const int* in_sizes, int n_in,
                              void* d_out, int out_size)
{
    const float* x       = (const float*)d_in[0];
    const float* f_ij    = (const float*)d_in[1];
    const float* rcut_ij = (const float*)d_in[2];
    const int*   idx_i   = (const int*)d_in[3];
    const int*   idx_j   = (const int*)d_in[4];
    const float* W_in2f  = (const float*)d_in[5];
    const float* W_filt1 = (const float*)d_in[6];
    const float* b_filt1 = (const float*)d_in[7];
    const float* W_filt2 = (const float*)d_in[8];
    const float* b_filt2 = (const float*)d_in[9];
    const float* W_out1  = (const float*)d_in[10];
    const float* b_out1  = (const float*)d_in[11];
    const float* W_out2  = (const float*)d_in[12];
    const float* b_out2  = (const float*)d_in[13];
    float* out = (float*)d_out;

    void* p_agg = nullptr;
    cudaGetSymbolAddress(&p_agg, g_agg);
    float* agg = (float*)p_agg;

    int nsm = 148;
    cudaDeviceGetAttribute(&nsm, cudaDevAttrMultiProcessorCount, 0);

    cudaFuncSetAttribute(h_kernel,
                         cudaFuncAttributeMaxDynamicSharedMemorySize, H_SMEMB);
    cudaFuncSetAttribute(edge_kernel,
                         cudaFuncAttributeMaxDynamicSharedMemorySize, E_SMEMB);
    cudaFuncSetAttribute(out_kernel,
                         cudaFuncAttributeMaxDynamicSharedMemorySize, O_SMEMB);

    // 0) pack weight fragments once
    prep_kernel<<<40, 256>>>(W_filt1, W_filt2, W_in2f, W_out1, W_out2);
    // 1) h = x @ W_in2f -> fp16, zero agg
    h_kernel<<<nsm, HT, H_SMEMB>>>(x, agg);
    // 2) fused edge kernel (M=32/warp)
    edge_kernel<<<nsm, ET, E_SMEMB>>>(f_ij, rcut_ij, idx_i, idx_j, b_filt1, b_filt2);
    // 3) fused output MLP
    out_kernel<<<nsm, OT, O_SMEMB>>>(agg, b_out1, b_out2, out);
}